// round 1
// baseline (speedup 1.0000x reference)
#include <cuda_runtime.h>
#include <math.h>

#define N_NODES 50000
#define N_EDGES 800000
#define IN_DIM  128
#define HID     96
#define OUT_DIM 64
#define MAX_REC 5

// ---------------- scratch (no allocations allowed) ----------------
__device__ float g_h[N_NODES * HID];
__device__ float g_agg[N_NODES * HID];
__device__ int   g_steps[N_NODES];
__device__ int   g_deg[N_NODES];
__device__ int   g_rowoff[N_NODES + 1];
__device__ int   g_cursor[N_NODES];
__device__ int   g_col[N_EDGES];
__device__ int   g_hist[8];
__device__ int   g_bcur[8];
__device__ int   g_order[N_NODES];
__device__ int   g_cnt[8];

// ---------------- init: zero degree + histogram ----------------
__global__ void k_init() {
    int i = blockIdx.x * blockDim.x + threadIdx.x;
    if (i < N_NODES) g_deg[i] = 0;
    if (i < 8) g_hist[i] = 0;
}

// ---------------- fused input GEMM + relu + tau/steps ----------------
// block: 128 threads, 32 nodes per block
// smem: xs[32*129] + ws[128*96] + ts[128*16]  (~73.9 KB dynamic)
__global__ __launch_bounds__(128) void k_input(
    const float* __restrict__ x, const float* __restrict__ w_in,
    const float* __restrict__ b_in, const float* __restrict__ tw1,
    const float* __restrict__ tb1, const float* __restrict__ tw2,
    const float* __restrict__ tb2)
{
    extern __shared__ float sm_in[];
    float* xs = sm_in;                // [32][129] padded
    float* ws = xs + 32 * 129;        // [128][96]  (k-major, same as w_in)
    float* ts = ws + 128 * 96;        // [128][16]
    int t = threadIdx.x;
    int node0 = blockIdx.x * 32;

    for (int idx = t; idx < 128 * 96; idx += 128) ws[idx] = w_in[idx];
    for (int idx = t; idx < 128 * 16; idx += 128) ts[idx] = tw1[idx];
    for (int idx = t; idx < 32 * 128; idx += 128) {
        int n = idx >> 7, k = idx & 127;
        int gn = node0 + n;
        xs[n * 129 + k] = (gn < N_NODES) ? x[gn * IN_DIM + k] : 0.f;
    }
    __syncthreads();

    int jt = t & 31;   // columns jt, jt+32, jt+64
    int nt = t >> 5;   // nodes nt, nt+4, ..., nt+28
    float acc[3][8];
#pragma unroll
    for (int jj = 0; jj < 3; jj++) {
        float b = b_in[jt + 32 * jj];
#pragma unroll
        for (int nn = 0; nn < 8; nn++) acc[jj][nn] = b;
    }
    for (int k = 0; k < 128; k++) {
        float w0 = ws[k * 96 + jt];
        float w1 = ws[k * 96 + jt + 32];
        float w2 = ws[k * 96 + jt + 64];
#pragma unroll
        for (int nn = 0; nn < 8; nn++) {
            float a = xs[(nt + 4 * nn) * 129 + k];
            acc[0][nn] += w0 * a;
            acc[1][nn] += w1 * a;
            acc[2][nn] += w2 * a;
        }
    }
#pragma unroll
    for (int nn = 0; nn < 8; nn++) {
        int gn = node0 + nt + 4 * nn;
        if (gn < N_NODES) {
#pragma unroll
            for (int jj = 0; jj < 3; jj++)
                g_h[gn * HID + jt + 32 * jj] = fmaxf(acc[jj][nn], 0.f);
        }
    }

    // tau path: one node per thread for t < 32
    if (t < 32) {
        int gn = node0 + t;
        if (gn < N_NODES) {
            float s = tb2[0];
            for (int j = 0; j < 16; j++) {
                float hh = tb1[j];
                for (int k = 0; k < 128; k++)
                    hh += xs[t * 129 + k] * ts[k * 16 + j];
                hh = fmaxf(hh, 0.f);
                s += hh * tw2[j];
            }
            // softplus = logaddexp(s, 0)
            float sp = fmaxf(s, 0.f) + log1pf(expf(-fabsf(s)));
            float inv = 1.0f / sp;
            int st = (inv >= (float)MAX_REC) ? MAX_REC : (int)inv;
            g_steps[gn] = st;
            atomicAdd(&g_hist[st], 1);
        }
    }
}

// ---------------- degree histogram ----------------
__global__ void k_deg(const int* __restrict__ ei) {
    int e = blockIdx.x * blockDim.x + threadIdx.x;
    if (e < N_EDGES) atomicAdd(&g_deg[ei[e]], 1);
}

// ---------------- single-block scan: rowoff/cursor + step buckets ----------------
__global__ __launch_bounds__(1024) void k_scan() {
    __shared__ int wsum[32];
    __shared__ int woff[32];
    __shared__ int total_s;
    __shared__ int carry_s;
    int t = threadIdx.x, lane = t & 31, wid = t >> 5;
    if (t == 0) carry_s = 0;
    __syncthreads();
    for (int base = 0; base < N_NODES; base += 1024) {
        int i = base + t;
        int v = (i < N_NODES) ? g_deg[i] : 0;
        int s = v;
#pragma unroll
        for (int o = 1; o < 32; o <<= 1) {
            int u = __shfl_up_sync(0xffffffffu, s, o);
            if (lane >= o) s += u;
        }
        if (lane == 31) wsum[wid] = s;
        __syncthreads();
        if (wid == 0) {
            int ws = wsum[lane];
            int ss = ws;
#pragma unroll
            for (int o = 1; o < 32; o <<= 1) {
                int u = __shfl_up_sync(0xffffffffu, ss, o);
                if (lane >= o) ss += u;
            }
            woff[lane] = ss - ws;
            if (lane == 31) total_s = ss;
        }
        __syncthreads();
        int excl = s - v + woff[wid] + carry_s;
        if (i < N_NODES) { g_rowoff[i] = excl; g_cursor[i] = excl; }
        __syncthreads();
        if (t == 0) carry_s += total_s;
        __syncthreads();
    }
    if (t == 0) {
        g_rowoff[N_NODES] = carry_s;  // == N_EDGES
        int suffix = 0;
        int start[6];
        for (int s = 5; s >= 0; s--) { start[s] = suffix; suffix += g_hist[s]; }
        for (int s = 0; s < 6; s++) g_bcur[s] = start[s];
        for (int it = 0; it < 5; it++) g_cnt[it] = start[it];  // #steps > it
    }
}

// ---------------- CSR fill ----------------
__global__ void k_csr(const int* __restrict__ ei) {
    int e = blockIdx.x * blockDim.x + threadIdx.x;
    if (e < N_EDGES) {
        int r = ei[e];
        int c = ei[N_EDGES + e];
        int pos = atomicAdd(&g_cursor[r], 1);
        g_col[pos] = c;
    }
}

// ---------------- counting sort nodes by steps (descending) ----------------
__global__ void k_order() {
    int i = blockIdx.x * blockDim.x + threadIdx.x;
    if (i < N_NODES) {
        int s = g_steps[i];
        int pos = atomicAdd(&g_bcur[s], 1);
        g_order[pos] = i;
    }
}

// ---------------- edge aggregation: warp per active node ----------------
__global__ __launch_bounds__(256) void k_agg(int it) {
    int w = blockIdx.x * 8 + (threadIdx.x >> 5);
    if (w >= g_cnt[it]) return;
    int node = g_order[w];
    int lane = threadIdx.x & 31;
    int base = g_rowoff[node], end = g_rowoff[node + 1];
    const float* hrow = g_h + (long long)node * HID;
    float hi0 = hrow[lane], hi1 = hrow[lane + 32], hi2 = hrow[lane + 64];
    float a0 = 0.f, a1 = 0.f, a2 = 0.f;
    for (int e0 = base; e0 < end; e0 += 32) {
        int c = (e0 + lane < end) ? g_col[e0 + lane] : 0;
        int m = min(32, end - e0);
        for (int i = 0; i < m; i++) {
            int cc = __shfl_sync(0xffffffffu, c, i);
            const float* hp = g_h + (long long)cc * HID;
            a0 += fabsf(hp[lane] - hi0);
            a1 += fabsf(hp[lane + 32] - hi1);
            a2 += fabsf(hp[lane + 64] - hi2);
        }
    }
    float* arow = g_agg + (long long)node * HID;
    arow[lane] = a0; arow[lane + 32] = a1; arow[lane + 64] = a2;
}

// ---------------- GRU cell on active nodes: 64-node tile, 256 threads ----------------
// smem: agg_s[64*100] + h_s[64*100] + wa_s[96*100] + wb_s[96*100] + nodes[64]
__global__ __launch_bounds__(256, 1) void k_gru(
    const float* __restrict__ wih, const float* __restrict__ whh,
    const float* __restrict__ bih, const float* __restrict__ bhh, int it)
{
    extern __shared__ float sm_g[];
    float* agg_s = sm_g;               // 6400
    float* h_s   = agg_s + 6400;       // 6400
    float* wa_s  = h_s + 6400;         // 9600
    float* wb_s  = wa_s + 9600;        // 9600
    int*   nodes_s = (int*)(wb_s + 9600);

    int t = threadIdx.x;
    int cnt = g_cnt[it];
    int tile0 = blockIdx.x * 64;
    if (tile0 >= cnt) return;
    int nvalid = min(64, cnt - tile0);

    for (int i = t; i < 64; i += 256)
        nodes_s[i] = g_order[tile0 + min(i, nvalid - 1)];
    __syncthreads();
    for (int idx = t; idx < 64 * 96; idx += 256) {
        int n = idx / 96, c = idx - n * 96;
        int gn = nodes_s[n];
        agg_s[n * 100 + c] = g_agg[gn * HID + c];
        h_s[n * 100 + c]   = g_h[gn * HID + c];
    }

    int nt = t & 7;    // nodes nt + 8*nn, nn in [0,8)
    int jt = t >> 3;   // gates jt + 32*jj, jj in [0,3)

    float r_g[3][8], z_g[3][8];

#pragma unroll
    for (int chunk = 0; chunk < 3; chunk++) {
        __syncthreads();
        const float* wsrc1 = wih + chunk * 96 * 96;
        const float* wsrc2 = whh + chunk * 96 * 96;
        for (int idx = t; idx < 96 * 96; idx += 256) {
            int jr = idx / 96, k = idx - jr * 96;
            wa_s[jr * 100 + k] = wsrc1[idx];
            wb_s[jr * 100 + k] = wsrc2[idx];
        }
        __syncthreads();

        if (chunk < 2) {
            float acc[3][8];
#pragma unroll
            for (int jj = 0; jj < 3; jj++) {
                float b = bih[chunk * 96 + jt + 32 * jj] + bhh[chunk * 96 + jt + 32 * jj];
#pragma unroll
                for (int nn = 0; nn < 8; nn++) acc[jj][nn] = b;
            }
#pragma unroll 2
            for (int k4 = 0; k4 < 24; k4++) {
                float4 wa[3], wb[3];
#pragma unroll
                for (int jj = 0; jj < 3; jj++) {
                    wa[jj] = *(const float4*)&wa_s[(jt + 32 * jj) * 100 + 4 * k4];
                    wb[jj] = *(const float4*)&wb_s[(jt + 32 * jj) * 100 + 4 * k4];
                }
#pragma unroll
                for (int nn = 0; nn < 8; nn++) {
                    float4 av = *(const float4*)&agg_s[(nt + 8 * nn) * 100 + 4 * k4];
                    float4 hv = *(const float4*)&h_s[(nt + 8 * nn) * 100 + 4 * k4];
#pragma unroll
                    for (int jj = 0; jj < 3; jj++) {
                        acc[jj][nn] += wa[jj].x * av.x + wa[jj].y * av.y +
                                       wa[jj].z * av.z + wa[jj].w * av.w +
                                       wb[jj].x * hv.x + wb[jj].y * hv.y +
                                       wb[jj].z * hv.z + wb[jj].w * hv.w;
                    }
                }
            }
#pragma unroll
            for (int jj = 0; jj < 3; jj++)
#pragma unroll
                for (int nn = 0; nn < 8; nn++) {
                    float sgv = 1.f / (1.f + expf(-acc[jj][nn]));
                    if (chunk == 0) r_g[jj][nn] = sgv; else z_g[jj][nn] = sgv;
                }
        } else {
            float ai[3][8], ah[3][8];
#pragma unroll
            for (int jj = 0; jj < 3; jj++) {
                float b1 = bih[192 + jt + 32 * jj];
                float b2 = bhh[192 + jt + 32 * jj];
#pragma unroll
                for (int nn = 0; nn < 8; nn++) { ai[jj][nn] = b1; ah[jj][nn] = b2; }
            }
#pragma unroll 2
            for (int k4 = 0; k4 < 24; k4++) {
                float4 wa[3], wb[3];
#pragma unroll
                for (int jj = 0; jj < 3; jj++) {
                    wa[jj] = *(const float4*)&wa_s[(jt + 32 * jj) * 100 + 4 * k4];
                    wb[jj] = *(const float4*)&wb_s[(jt + 32 * jj) * 100 + 4 * k4];
                }
#pragma unroll
                for (int nn = 0; nn < 8; nn++) {
                    float4 av = *(const float4*)&agg_s[(nt + 8 * nn) * 100 + 4 * k4];
                    float4 hv = *(const float4*)&h_s[(nt + 8 * nn) * 100 + 4 * k4];
#pragma unroll
                    for (int jj = 0; jj < 3; jj++) {
                        ai[jj][nn] += wa[jj].x * av.x + wa[jj].y * av.y +
                                      wa[jj].z * av.z + wa[jj].w * av.w;
                        ah[jj][nn] += wb[jj].x * hv.x + wb[jj].y * hv.y +
                                      wb[jj].z * hv.z + wb[jj].w * hv.w;
                    }
                }
            }
            float hnew[3][8];
#pragma unroll
            for (int jj = 0; jj < 3; jj++)
#pragma unroll
                for (int nn = 0; nn < 8; nn++) {
                    float nv = tanhf(ai[jj][nn] + r_g[jj][nn] * ah[jj][nn]);
                    float hold = h_s[(nt + 8 * nn) * 100 + jt + 32 * jj];
                    hnew[jj][nn] = (1.f - z_g[jj][nn]) * nv + z_g[jj][nn] * hold;
                }
            __syncthreads();  // done reading agg_s / h_s before reuse
#pragma unroll
            for (int jj = 0; jj < 3; jj++)
#pragma unroll
                for (int nn = 0; nn < 8; nn++)
                    agg_s[(nt + 8 * nn) * 100 + jt + 32 * jj] = hnew[jj][nn];
            __syncthreads();
            for (int idx = t; idx < nvalid * 96; idx += 256) {
                int n = idx / 96, c = idx - n * 96;
                g_h[nodes_s[n] * HID + c] = agg_s[n * 100 + c];
            }
        }
    }
}

// ---------------- output GEMM: h @ w_out + b_out ----------------
__global__ __launch_bounds__(256) void k_out(
    const float* __restrict__ wo, const float* __restrict__ bo,
    float* __restrict__ out)
{
    __shared__ float ws[96 * 64];
    __shared__ float hs[32 * 97];
    int t = threadIdx.x;
    int node0 = blockIdx.x * 32;
    for (int idx = t; idx < 96 * 64; idx += 256) ws[idx] = wo[idx];
    for (int idx = t; idx < 32 * 96; idx += 256) {
        int n = idx / 96, k = idx - n * 96;
        int gn = node0 + n;
        hs[n * 97 + k] = (gn < N_NODES) ? g_h[gn * HID + k] : 0.f;
    }
    __syncthreads();
    int j = t & 63, nt = t >> 6;  // nodes nt + 4*nn
    float acc[8];
#pragma unroll
    for (int nn = 0; nn < 8; nn++) acc[nn] = bo[j];
    for (int k = 0; k < 96; k++) {
        float w = ws[k * 64 + j];
#pragma unroll
        for (int nn = 0; nn < 8; nn++)
            acc[nn] += hs[(nt + 4 * nn) * 97 + k] * w;
    }
#pragma unroll
    for (int nn = 0; nn < 8; nn++) {
        int gn = node0 + nt + 4 * nn;
        if (gn < N_NODES) out[gn * OUT_DIM + j] = acc[nn];
    }
}

// ---------------- launch ----------------
extern "C" void kernel_launch(void* const* d_in, const int* in_sizes, int n_in,
                              void* d_out, int out_size)
{
    const float* x    = (const float*)d_in[0];
    const int*   ei   = (const int*)d_in[1];
    const float* w_in = (const float*)d_in[2];
    const float* b_in = (const float*)d_in[3];
    const float* tw1  = (const float*)d_in[4];
    const float* tb1  = (const float*)d_in[5];
    const float* tw2  = (const float*)d_in[6];
    const float* tb2  = (const float*)d_in[7];
    const float* wih  = (const float*)d_in[8];
    const float* whh  = (const float*)d_in[9];
    const float* bih  = (const float*)d_in[10];
    const float* bhh  = (const float*)d_in[11];
    const float* wo   = (const float*)d_in[12];
    const float* bo   = (const float*)d_in[13];
    float* out = (float*)d_out;

    const int smem_in  = (32 * 129 + 128 * 96 + 128 * 16) * 4;           // 73856 B
    const int smem_gru = (6400 * 2 + 9600 * 2) * 4 + 64 * 4;             // 128256 B
    cudaFuncSetAttribute(k_input, cudaFuncAttributeMaxDynamicSharedMemorySize, smem_in);
    cudaFuncSetAttribute(k_gru,   cudaFuncAttributeMaxDynamicSharedMemorySize, smem_gru);

    k_init<<<(N_NODES + 255) / 256, 256>>>();
    k_input<<<(N_NODES + 31) / 32, 128, smem_in>>>(x, w_in, b_in, tw1, tb1, tw2, tb2);
    k_deg<<<(N_EDGES + 255) / 256, 256>>>(ei);
    k_scan<<<1, 1024>>>();
    k_csr<<<(N_EDGES + 255) / 256, 256>>>(ei);
    k_order<<<(N_NODES + 255) / 256, 256>>>();

    for (int it = 0; it < MAX_REC; it++) {
        k_agg<<<(N_NODES + 7) / 8, 256>>>(it);
        k_gru<<<(N_NODES + 63) / 64, 256, smem_gru>>>(wih, whh, bih, bhh, it);
    }
    k_out<<<(N_NODES + 31) / 32, 256>>>(wo, bo, out);
}

// round 2
// speedup vs baseline: 1.0808x; 1.0808x over previous
#include <cuda_runtime.h>
#include <math.h>

#define N_NODES 50000
#define N_EDGES 800000
#define IN_DIM  128
#define HID     96
#define OUT_DIM 64
#define MAX_REC 5
#define SCAN_NB ((N_NODES + 1023) / 1024)   // 49

typedef unsigned long long u64;

// ---------------- scratch (no allocations allowed) ----------------
__device__ float g_h[N_NODES * HID];
__device__ float g_agg[N_NODES * HID];
__device__ int   g_steps[N_NODES];
__device__ int   g_deg[N_NODES];
__device__ int   g_rowoff[N_NODES + 1];
__device__ int   g_cursor[N_NODES];
__device__ int   g_col[N_EDGES];
__device__ int   g_hist[8];
__device__ int   g_bcur[8];
__device__ int   g_order[N_NODES];
__device__ int   g_cnt[8];
__device__ int   g_bsum[64];
__device__ int   g_boff[64];
__device__ float g_wt_ih[3 * HID * HID];   // [chunk][k][j]
__device__ float g_wt_hh[3 * HID * HID];

// ---------------- f32x2 helpers ----------------
__device__ __forceinline__ u64 ffma2(u64 a, u64 b, u64 c) {
    u64 d;
    asm("fma.rn.f32x2 %0, %1, %2, %3;" : "=l"(d) : "l"(a), "l"(b), "l"(c));
    return d;
}
__device__ __forceinline__ u64 pack2(float x, float y) {
    u64 r;
    asm("mov.b64 %0, {%1, %2};" : "=l"(r) : "f"(x), "f"(y));
    return r;
}
__device__ __forceinline__ float2 unpack2(u64 v) {
    float2 r;
    asm("mov.b64 {%0, %1}, %2;" : "=f"(r.x), "=f"(r.y) : "l"(v));
    return r;
}

// ---------------- init ----------------
__global__ void k_init() {
    int i = blockIdx.x * blockDim.x + threadIdx.x;
    if (i < N_NODES) g_deg[i] = 0;
    if (i < 8) g_hist[i] = 0;
}

// ---------------- weight transpose: [j][k] -> [chunk][k][j] ----------------
__global__ void k_wt(const float* __restrict__ wih, const float* __restrict__ whh) {
    int idx = blockIdx.x * 256 + threadIdx.x;
    if (idx < 3 * HID * HID) {
        int chunk = idx / (HID * HID);
        int r = idx - chunk * HID * HID;
        int k = r / HID, j = r - k * HID;
        g_wt_ih[idx] = wih[(chunk * HID + j) * HID + k];
        g_wt_hh[idx] = whh[(chunk * HID + j) * HID + k];
    }
}

// ---------------- fused input GEMM + relu + tau/steps ----------------
__global__ __launch_bounds__(128) void k_input(
    const float* __restrict__ x, const float* __restrict__ w_in,
    const float* __restrict__ b_in, const float* __restrict__ tw1,
    const float* __restrict__ tb1, const float* __restrict__ tw2,
    const float* __restrict__ tb2)
{
    extern __shared__ float sm_in[];
    float* xs = sm_in;                // [32][129]
    float* ws = xs + 32 * 129;        // [128][96]
    float* ts = ws + 128 * 96;        // [128][16]
    int t = threadIdx.x;
    int node0 = blockIdx.x * 32;

    for (int idx = t; idx < 128 * 96; idx += 128) ws[idx] = w_in[idx];
    for (int idx = t; idx < 128 * 16; idx += 128) ts[idx] = tw1[idx];
    for (int idx = t; idx < 32 * 128; idx += 128) {
        int n = idx >> 7, k = idx & 127;
        int gn = node0 + n;
        xs[n * 129 + k] = (gn < N_NODES) ? x[gn * IN_DIM + k] : 0.f;
    }
    __syncthreads();

    int jt = t & 31;
    int nt = t >> 5;
    float acc[3][8];
#pragma unroll
    for (int jj = 0; jj < 3; jj++) {
        float b = b_in[jt + 32 * jj];
#pragma unroll
        for (int nn = 0; nn < 8; nn++) acc[jj][nn] = b;
    }
    for (int k = 0; k < 128; k++) {
        float w0 = ws[k * 96 + jt];
        float w1 = ws[k * 96 + jt + 32];
        float w2 = ws[k * 96 + jt + 64];
#pragma unroll
        for (int nn = 0; nn < 8; nn++) {
            float a = xs[(nt + 4 * nn) * 129 + k];
            acc[0][nn] += w0 * a;
            acc[1][nn] += w1 * a;
            acc[2][nn] += w2 * a;
        }
    }
#pragma unroll
    for (int nn = 0; nn < 8; nn++) {
        int gn = node0 + nt + 4 * nn;
        if (gn < N_NODES) {
#pragma unroll
            for (int jj = 0; jj < 3; jj++)
                g_h[gn * HID + jt + 32 * jj] = fmaxf(acc[jj][nn], 0.f);
        }
    }

    if (t < 32) {
        int gn = node0 + t;
        if (gn < N_NODES) {
            float s = tb2[0];
            for (int j = 0; j < 16; j++) {
                float hh = tb1[j];
                for (int k = 0; k < 128; k++)
                    hh += xs[t * 129 + k] * ts[k * 16 + j];
                hh = fmaxf(hh, 0.f);
                s += hh * tw2[j];
            }
            float sp = fmaxf(s, 0.f) + log1pf(expf(-fabsf(s)));
            float inv = 1.0f / sp;
            int st = (inv >= (float)MAX_REC) ? MAX_REC : (int)inv;
            g_steps[gn] = st;
            atomicAdd(&g_hist[st], 1);
        }
    }
}

// ---------------- degree histogram ----------------
__global__ void k_deg(const int* __restrict__ ei) {
    int e = blockIdx.x * blockDim.x + threadIdx.x;
    if (e < N_EDGES) atomicAdd(&g_deg[ei[e]], 1);
}

// ---------------- multi-block scan ----------------
__global__ __launch_bounds__(1024) void k_scan1() {
    __shared__ int wsum[32];
    __shared__ int woff[32];
    int t = threadIdx.x, lane = t & 31, wid = t >> 5;
    int i = blockIdx.x * 1024 + t;
    int v = (i < N_NODES) ? g_deg[i] : 0;
    int s = v;
#pragma unroll
    for (int o = 1; o < 32; o <<= 1) {
        int u = __shfl_up_sync(0xffffffffu, s, o);
        if (lane >= o) s += u;
    }
    if (lane == 31) wsum[wid] = s;
    __syncthreads();
    if (wid == 0) {
        int ws = wsum[lane];
        int ss = ws;
#pragma unroll
        for (int o = 1; o < 32; o <<= 1) {
            int u = __shfl_up_sync(0xffffffffu, ss, o);
            if (lane >= o) ss += u;
        }
        woff[lane] = ss - ws;
        if (lane == 31) g_bsum[blockIdx.x] = ss;
    }
    __syncthreads();
    if (i < N_NODES) g_rowoff[i] = s - v + woff[wid];
}

__global__ void k_scan2() {
    __shared__ int sh[64];
    int t = threadIdx.x;
    sh[t] = (t < SCAN_NB) ? g_bsum[t] : 0;
    __syncthreads();
    if (t == 0) {
        int run = 0;
        for (int b = 0; b < SCAN_NB; b++) { g_boff[b] = run; run += sh[b]; }
        g_rowoff[N_NODES] = run;
        int suffix = 0;
        int start[6];
        for (int s = 5; s >= 0; s--) { start[s] = suffix; suffix += g_hist[s]; }
        for (int s = 0; s < 6; s++) g_bcur[s] = start[s];
        for (int it = 0; it < 5; it++) g_cnt[it] = start[it];
    }
}

__global__ __launch_bounds__(1024) void k_scan3() {
    int i = blockIdx.x * 1024 + threadIdx.x;
    if (i < N_NODES) {
        int v = g_rowoff[i] + g_boff[blockIdx.x];
        g_rowoff[i] = v;
        g_cursor[i] = v;
    }
}

// ---------------- CSR fill ----------------
__global__ void k_csr(const int* __restrict__ ei) {
    int e = blockIdx.x * blockDim.x + threadIdx.x;
    if (e < N_EDGES) {
        int r = ei[e];
        int c = ei[N_EDGES + e];
        int pos = atomicAdd(&g_cursor[r], 1);
        g_col[pos] = c;
    }
}

// ---------------- counting sort by steps (descending) ----------------
__global__ void k_order() {
    int i = blockIdx.x * blockDim.x + threadIdx.x;
    if (i < N_NODES) {
        int s = g_steps[i];
        int pos = atomicAdd(&g_bcur[s], 1);
        g_order[pos] = i;
    }
}

// ---------------- edge aggregation: warp per active node ----------------
__global__ __launch_bounds__(256) void k_agg(int it) {
    int w = blockIdx.x * 8 + (threadIdx.x >> 5);
    if (w >= g_cnt[it]) return;
    int node = g_order[w];
    int lane = threadIdx.x & 31;
    int base = g_rowoff[node], end = g_rowoff[node + 1];
    const float* hrow = g_h + (long long)node * HID;
    float hi0 = hrow[lane], hi1 = hrow[lane + 32], hi2 = hrow[lane + 64];
    float a0 = 0.f, a1 = 0.f, a2 = 0.f;
    for (int e0 = base; e0 < end; e0 += 32) {
        int c = (e0 + lane < end) ? g_col[e0 + lane] : 0;
        int m = min(32, end - e0);
        for (int i = 0; i < m; i++) {
            int cc = __shfl_sync(0xffffffffu, c, i);
            const float* hp = g_h + (long long)cc * HID;
            a0 += fabsf(hp[lane] - hi0);
            a1 += fabsf(hp[lane + 32] - hi1);
            a2 += fabsf(hp[lane + 64] - hi2);
        }
    }
    float* arow = g_agg + (long long)node * HID;
    arow[lane] = a0; arow[lane + 32] = a1; arow[lane + 64] = a2;
}

// ---------------- GRU with packed f32x2 ----------------
// 64 nodes/tile, 256 threads. Thread = (ct in [0,16), ng in [0,16)).
// ct handles column pairs {ct, ct+16, ct+32} (cols 2p, 2p+1); ng handles 4 nodes.
// smem: agg_s[64*100] + h_s[64*100] + wa_t[96*96] + wb_t[96*96] + nodes[64]
__global__ __launch_bounds__(256, 1) void k_gru(
    const float* __restrict__ bih, const float* __restrict__ bhh, int it)
{
    extern __shared__ float sm_g[];
    float* agg_s = sm_g;               // 6400
    float* h_s   = agg_s + 6400;       // 6400
    float* wa_t  = h_s + 6400;         // 9216  [k][j]
    float* wb_t  = wa_t + 9216;        // 9216
    int*   nodes_s = (int*)(wb_t + 9216);

    int t = threadIdx.x;
    int cnt = g_cnt[it];
    int tile0 = blockIdx.x * 64;
    if (tile0 >= cnt) return;
    int nvalid = min(64, cnt - tile0);

    if (t < 64) nodes_s[t] = g_order[tile0 + min(t, nvalid - 1)];
    __syncthreads();
    for (int idx = t; idx < 64 * 96; idx += 256) {
        int n = idx / 96, c = idx - n * 96;
        int gn = nodes_s[n];
        agg_s[n * 100 + c] = g_agg[gn * HID + c];
        h_s[n * 100 + c]   = g_h[gn * HID + c];
    }

    int ct = t & 15;
    int ng = t >> 4;
    int nbase = ng * 4;

    u64 r_g[3][4], z_g[3][4];

#pragma unroll
    for (int chunk = 0; chunk < 3; chunk++) {
        __syncthreads();   // activations ready (c0) / previous chunk done reading weights
        const float* srcA = g_wt_ih + chunk * 9216;
        const float* srcB = g_wt_hh + chunk * 9216;
        for (int idx = t; idx < 9216; idx += 256) {
            wa_t[idx] = srcA[idx];
            wb_t[idx] = srcB[idx];
        }
        __syncthreads();

        if (chunk < 2) {
            u64 acc[3][4];
#pragma unroll
            for (int pp = 0; pp < 3; pp++) {
                int p = ct + 16 * pp;
                float2 b1 = *(const float2*)&bih[chunk * 96 + 2 * p];
                float2 b2 = *(const float2*)&bhh[chunk * 96 + 2 * p];
                u64 bp = pack2(b1.x + b2.x, b1.y + b2.y);
#pragma unroll
                for (int nn = 0; nn < 4; nn++) acc[pp][nn] = bp;
            }
#pragma unroll 2
            for (int k = 0; k < 96; k++) {
                u64 wa[3], wb[3];
#pragma unroll
                for (int pp = 0; pp < 3; pp++) {
                    int p = ct + 16 * pp;
                    wa[pp] = *(const u64*)&wa_t[k * 96 + 2 * p];
                    wb[pp] = *(const u64*)&wb_t[k * 96 + 2 * p];
                }
#pragma unroll
                for (int nn = 0; nn < 4; nn++) {
                    float a  = agg_s[(nbase + nn) * 100 + k];
                    float hv = h_s[(nbase + nn) * 100 + k];
                    u64 a2 = pack2(a, a);
                    u64 h2 = pack2(hv, hv);
#pragma unroll
                    for (int pp = 0; pp < 3; pp++) {
                        acc[pp][nn] = ffma2(wa[pp], a2, acc[pp][nn]);
                        acc[pp][nn] = ffma2(wb[pp], h2, acc[pp][nn]);
                    }
                }
            }
#pragma unroll
            for (int pp = 0; pp < 3; pp++)
#pragma unroll
                for (int nn = 0; nn < 4; nn++) {
                    float2 g = unpack2(acc[pp][nn]);
                    float s0 = 1.f / (1.f + expf(-g.x));
                    float s1 = 1.f / (1.f + expf(-g.y));
                    if (chunk == 0) r_g[pp][nn] = pack2(s0, s1);
                    else            z_g[pp][nn] = pack2(s0, s1);
                }
        } else {
            u64 ai[3][4], ah[3][4];
#pragma unroll
            for (int pp = 0; pp < 3; pp++) {
                int p = ct + 16 * pp;
                float2 b1 = *(const float2*)&bih[192 + 2 * p];
                float2 b2 = *(const float2*)&bhh[192 + 2 * p];
                u64 bi = pack2(b1.x, b1.y);
                u64 bh = pack2(b2.x, b2.y);
#pragma unroll
                for (int nn = 0; nn < 4; nn++) { ai[pp][nn] = bi; ah[pp][nn] = bh; }
            }
#pragma unroll 2
            for (int k = 0; k < 96; k++) {
                u64 wa[3], wb[3];
#pragma unroll
                for (int pp = 0; pp < 3; pp++) {
                    int p = ct + 16 * pp;
                    wa[pp] = *(const u64*)&wa_t[k * 96 + 2 * p];
                    wb[pp] = *(const u64*)&wb_t[k * 96 + 2 * p];
                }
#pragma unroll
                for (int nn = 0; nn < 4; nn++) {
                    float a  = agg_s[(nbase + nn) * 100 + k];
                    float hv = h_s[(nbase + nn) * 100 + k];
                    u64 a2 = pack2(a, a);
                    u64 h2 = pack2(hv, hv);
#pragma unroll
                    for (int pp = 0; pp < 3; pp++) {
                        ai[pp][nn] = ffma2(wa[pp], a2, ai[pp][nn]);
                        ah[pp][nn] = ffma2(wb[pp], h2, ah[pp][nn]);
                    }
                }
            }
#pragma unroll
            for (int pp = 0; pp < 3; pp++) {
                int col = 2 * (ct + 16 * pp);
#pragma unroll
                for (int nn = 0; nn < 4; nn++) {
                    float2 vi = unpack2(ai[pp][nn]);
                    float2 vh = unpack2(ah[pp][nn]);
                    float2 rr = unpack2(r_g[pp][nn]);
                    float2 zz = unpack2(z_g[pp][nn]);
                    int n = nbase + nn;
                    float hold0 = h_s[n * 100 + col];
                    float hold1 = h_s[n * 100 + col + 1];
                    float nv0 = tanhf(vi.x + rr.x * vh.x);
                    float nv1 = tanhf(vi.y + rr.y * vh.y);
                    float h0 = (1.f - zz.x) * nv0 + zz.x * hold0;
                    float h1 = (1.f - zz.y) * nv1 + zz.y * hold1;
                    int gn = nodes_s[n];
                    *(float2*)&g_h[gn * HID + col] = make_float2(h0, h1);
                }
            }
        }
    }
}

// ---------------- output GEMM: h @ w_out + b_out ----------------
__global__ __launch_bounds__(256) void k_out(
    const float* __restrict__ wo, const float* __restrict__ bo,
    float* __restrict__ out)
{
    __shared__ float ws[96 * 64];
    __shared__ float hs[32 * 97];
    int t = threadIdx.x;
    int node0 = blockIdx.x * 32;
    for (int idx = t; idx < 96 * 64; idx += 256) ws[idx] = wo[idx];
    for (int idx = t; idx < 32 * 96; idx += 256) {
        int n = idx / 96, k = idx - n * 96;
        int gn = node0 + n;
        hs[n * 97 + k] = (gn < N_NODES) ? g_h[gn * HID + k] : 0.f;
    }
    __syncthreads();
    int j = t & 63, nt = t >> 6;
    float acc[8];
#pragma unroll
    for (int nn = 0; nn < 8; nn++) acc[nn] = bo[j];
    for (int k = 0; k < 96; k++) {
        float w = ws[k * 64 + j];
#pragma unroll
        for (int nn = 0; nn < 8; nn++)
            acc[nn] += hs[(nt + 4 * nn) * 97 + k] * w;
    }
#pragma unroll
    for (int nn = 0; nn < 8; nn++) {
        int gn = node0 + nt + 4 * nn;
        if (gn < N_NODES) out[gn * OUT_DIM + j] = acc[nn];
    }
}

// ---------------- launch ----------------
extern "C" void kernel_launch(void* const* d_in, const int* in_sizes, int n_in,
                              void* d_out, int out_size)
{
    const float* x    = (const float*)d_in[0];
    const int*   ei   = (const int*)d_in[1];
    const float* w_in = (const float*)d_in[2];
    const float* b_in = (const float*)d_in[3];
    const float* tw1  = (const float*)d_in[4];
    const float* tb1  = (const float*)d_in[5];
    const float* tw2  = (const float*)d_in[6];
    const float* tb2  = (const float*)d_in[7];
    const float* wih  = (const float*)d_in[8];
    const float* whh  = (const float*)d_in[9];
    const float* bih  = (const float*)d_in[10];
    const float* bhh  = (const float*)d_in[11];
    const float* wo   = (const float*)d_in[12];
    const float* bo   = (const float*)d_in[13];
    float* out = (float*)d_out;

    const int smem_in  = (32 * 129 + 128 * 96 + 128 * 16) * 4;              // 73856 B
    const int smem_gru = (6400 * 2 + 9216 * 2) * 4 + 64 * 4;                // 125184 B
    cudaFuncSetAttribute(k_input, cudaFuncAttributeMaxDynamicSharedMemorySize, smem_in);
    cudaFuncSetAttribute(k_gru,   cudaFuncAttributeMaxDynamicSharedMemorySize, smem_gru);

    k_init<<<(N_NODES + 255) / 256, 256>>>();
    k_wt<<<(3 * HID * HID + 255) / 256, 256>>>(wih, whh);
    k_input<<<(N_NODES + 31) / 32, 128, smem_in>>>(x, w_in, b_in, tw1, tb1, tw2, tb2);
    k_deg<<<(N_EDGES + 255) / 256, 256>>>(ei);
    k_scan1<<<SCAN_NB, 1024>>>();
    k_scan2<<<1, 64>>>();
    k_scan3<<<SCAN_NB, 1024>>>();
    k_csr<<<(N_EDGES + 255) / 256, 256>>>(ei);
    k_order<<<(N_NODES + 255) / 256, 256>>>();

    for (int it = 0; it < MAX_REC; it++) {
        k_agg<<<(N_NODES + 7) / 8, 256>>>(it);
        k_gru<<<(N_NODES + 63) / 64, 256, smem_gru>>>(bih, bhh, it);
    }
    k_out<<<(N_NODES + 31) / 32, 256>>>(wo, bo, out);
}

// round 3
// speedup vs baseline: 1.1539x; 1.0677x over previous
#include <cuda_runtime.h>
#include <math.h>

#define N_NODES 50000
#define N_EDGES 800000
#define IN_DIM  128
#define HID     96
#define OUT_DIM 64
#define MAX_REC 5
#define SCAN_NB ((N_NODES + 1023) / 1024)   // 49

typedef unsigned long long u64;

// ---------------- scratch (no allocations allowed) ----------------
__device__ float g_h[N_NODES * HID];
__device__ float g_agg[N_NODES * HID];
__device__ int   g_steps[N_NODES];
__device__ int   g_deg[N_NODES];
__device__ int   g_rowoff[N_NODES + 1];
__device__ int   g_cursor[N_NODES];
__device__ int   g_col[N_EDGES];
__device__ int   g_hist[8];
__device__ int   g_bcur[8];
__device__ int   g_order[N_NODES];
__device__ int   g_cnt[8];
__device__ int   g_bsum[64];
__device__ int   g_boff[64];
__device__ float g_wt_ih[3 * HID * HID];   // [chunk][k][j]
__device__ float g_wt_hh[3 * HID * HID];

// ---------------- f32x2 helpers ----------------
__device__ __forceinline__ u64 ffma2(u64 a, u64 b, u64 c) {
    u64 d;
    asm("fma.rn.f32x2 %0, %1, %2, %3;" : "=l"(d) : "l"(a), "l"(b), "l"(c));
    return d;
}
__device__ __forceinline__ u64 pack2(float x, float y) {
    u64 r;
    asm("mov.b64 %0, {%1, %2};" : "=l"(r) : "f"(x), "f"(y));
    return r;
}
__device__ __forceinline__ float2 unpack2(u64 v) {
    float2 r;
    asm("mov.b64 {%0, %1}, %2;" : "=f"(r.x), "=f"(r.y) : "l"(v));
    return r;
}

// ---------------- fused init + weight transpose ----------------
__global__ void k_initwt(const float* __restrict__ wih, const float* __restrict__ whh) {
    int i = blockIdx.x * 256 + threadIdx.x;
    if (i < N_NODES) g_deg[i] = 0;
    if (i < 8) g_hist[i] = 0;
    if (i < 3 * HID * HID) {
        int chunk = i / (HID * HID);
        int r = i - chunk * HID * HID;
        int k = r / HID, j = r - k * HID;
        g_wt_ih[i] = wih[(chunk * HID + j) * HID + k];
        g_wt_hh[i] = whh[(chunk * HID + j) * HID + k];
    }
}

// ---------------- degree histogram ----------------
__global__ void k_deg(const int* __restrict__ ei) {
    int e = blockIdx.x * blockDim.x + threadIdx.x;
    if (e < N_EDGES) atomicAdd(&g_deg[ei[e]], 1);
}

// ---------------- multi-block scan ----------------
__global__ __launch_bounds__(1024) void k_scan1() {
    __shared__ int wsum[32];
    __shared__ int woff[32];
    int t = threadIdx.x, lane = t & 31, wid = t >> 5;
    int i = blockIdx.x * 1024 + t;
    int v = (i < N_NODES) ? g_deg[i] : 0;
    int s = v;
#pragma unroll
    for (int o = 1; o < 32; o <<= 1) {
        int u = __shfl_up_sync(0xffffffffu, s, o);
        if (lane >= o) s += u;
    }
    if (lane == 31) wsum[wid] = s;
    __syncthreads();
    if (wid == 0) {
        int ws = wsum[lane];
        int ss = ws;
#pragma unroll
        for (int o = 1; o < 32; o <<= 1) {
            int u = __shfl_up_sync(0xffffffffu, ss, o);
            if (lane >= o) ss += u;
        }
        woff[lane] = ss - ws;
        if (lane == 31) g_bsum[blockIdx.x] = ss;
    }
    __syncthreads();
    if (i < N_NODES) g_rowoff[i] = s - v + woff[wid];
}

// ---------------- fused input GEMM + relu + tau/steps ----------------
__global__ __launch_bounds__(128) void k_input(
    const float* __restrict__ x, const float* __restrict__ w_in,
    const float* __restrict__ b_in, const float* __restrict__ tw1,
    const float* __restrict__ tb1, const float* __restrict__ tw2,
    const float* __restrict__ tb2)
{
    extern __shared__ float sm_in[];
    float* xs = sm_in;                // [32][129]
    float* ws = xs + 32 * 129;        // [128][96]
    float* ts = ws + 128 * 96;        // [128][16]
    int t = threadIdx.x;
    int node0 = blockIdx.x * 32;

    for (int idx = t; idx < 128 * 96; idx += 128) ws[idx] = w_in[idx];
    for (int idx = t; idx < 128 * 16; idx += 128) ts[idx] = tw1[idx];
    for (int idx = t; idx < 32 * 128; idx += 128) {
        int n = idx >> 7, k = idx & 127;
        int gn = node0 + n;
        xs[n * 129 + k] = (gn < N_NODES) ? x[gn * IN_DIM + k] : 0.f;
    }
    __syncthreads();

    int jt = t & 31;
    int nt = t >> 5;
    float acc[3][8];
#pragma unroll
    for (int jj = 0; jj < 3; jj++) {
        float b = b_in[jt + 32 * jj];
#pragma unroll
        for (int nn = 0; nn < 8; nn++) acc[jj][nn] = b;
    }
    for (int k = 0; k < 128; k++) {
        float w0 = ws[k * 96 + jt];
        float w1 = ws[k * 96 + jt + 32];
        float w2 = ws[k * 96 + jt + 64];
#pragma unroll
        for (int nn = 0; nn < 8; nn++) {
            float a = xs[(nt + 4 * nn) * 129 + k];
            acc[0][nn] += w0 * a;
            acc[1][nn] += w1 * a;
            acc[2][nn] += w2 * a;
        }
    }
#pragma unroll
    for (int nn = 0; nn < 8; nn++) {
        int gn = node0 + nt + 4 * nn;
        if (gn < N_NODES) {
#pragma unroll
            for (int jj = 0; jj < 3; jj++)
                g_h[gn * HID + jt + 32 * jj] = fmaxf(acc[jj][nn], 0.f);
        }
    }

    if (t < 32) {
        int gn = node0 + t;
        if (gn < N_NODES) {
            float s = tb2[0];
            for (int j = 0; j < 16; j++) {
                float hh = tb1[j];
                for (int k = 0; k < 128; k++)
                    hh += xs[t * 129 + k] * ts[k * 16 + j];
                hh = fmaxf(hh, 0.f);
                s += hh * tw2[j];
            }
            float sp = fmaxf(s, 0.f) + log1pf(expf(-fabsf(s)));
            float inv = 1.0f / sp;
            int st = (inv >= (float)MAX_REC) ? MAX_REC : (int)inv;
            g_steps[gn] = st;
            atomicAdd(&g_hist[st], 1);
        }
    }
}

__global__ void k_scan2() {
    __shared__ int sh[64];
    int t = threadIdx.x;
    sh[t] = (t < SCAN_NB) ? g_bsum[t] : 0;
    __syncthreads();
    if (t == 0) {
        int run = 0;
        for (int b = 0; b < SCAN_NB; b++) { g_boff[b] = run; run += sh[b]; }
        g_rowoff[N_NODES] = run;
        int suffix = 0;
        int start[6];
        for (int s = 5; s >= 0; s--) { start[s] = suffix; suffix += g_hist[s]; }
        for (int s = 0; s < 6; s++) g_bcur[s] = start[s];
        for (int it = 0; it < 5; it++) g_cnt[it] = start[it];
    }
}

__global__ __launch_bounds__(1024) void k_scan3() {
    int i = blockIdx.x * 1024 + threadIdx.x;
    if (i < N_NODES) {
        int v = g_rowoff[i] + g_boff[blockIdx.x];
        g_rowoff[i] = v;
        g_cursor[i] = v;
    }
}

// ---------------- CSR fill ----------------
__global__ void k_csr(const int* __restrict__ ei) {
    int e = blockIdx.x * blockDim.x + threadIdx.x;
    if (e < N_EDGES) {
        int r = ei[e];
        int c = ei[N_EDGES + e];
        int pos = atomicAdd(&g_cursor[r], 1);
        g_col[pos] = c;
    }
}

// ---------------- counting sort by steps (descending) ----------------
__global__ void k_order() {
    int i = blockIdx.x * blockDim.x + threadIdx.x;
    if (i < N_NODES) {
        int s = g_steps[i];
        int pos = atomicAdd(&g_bcur[s], 1);
        g_order[pos] = i;
    }
}

// ---------------- edge aggregation: warp/node, 4 edges in flight ----------------
__global__ __launch_bounds__(256) void k_agg(int it) {
    int w = blockIdx.x * 8 + (threadIdx.x >> 5);
    if (w >= g_cnt[it]) return;
    int node = g_order[w];
    int lane = threadIdx.x & 31;
    int grp = lane >> 3;       // edge subgroup 0..3
    int l8  = lane & 7;        // float4 slot within row
    int base = g_rowoff[node], end = g_rowoff[node + 1];

    const float4* hi4 = (const float4*)(g_h + node * HID);
    float4 hi0 = hi4[l8], hi1 = hi4[l8 + 8], hi2 = hi4[l8 + 16];
    float4 a0 = {0,0,0,0}, a1 = {0,0,0,0}, a2 = {0,0,0,0};

    for (int e = base + grp; e < end; e += 4) {
        int cc = g_col[e];
        const float4* hp = (const float4*)(g_h + cc * HID);
        float4 v0 = hp[l8], v1 = hp[l8 + 8], v2 = hp[l8 + 16];
        a0.x += fabsf(v0.x - hi0.x); a0.y += fabsf(v0.y - hi0.y);
        a0.z += fabsf(v0.z - hi0.z); a0.w += fabsf(v0.w - hi0.w);
        a1.x += fabsf(v1.x - hi1.x); a1.y += fabsf(v1.y - hi1.y);
        a1.z += fabsf(v1.z - hi1.z); a1.w += fabsf(v1.w - hi1.w);
        a2.x += fabsf(v2.x - hi2.x); a2.y += fabsf(v2.y - hi2.y);
        a2.z += fabsf(v2.z - hi2.z); a2.w += fabsf(v2.w - hi2.w);
    }
    // reduce over the 4 subgroups (lanes differing in bits 3,4)
#pragma unroll
    for (int off = 8; off < 32; off <<= 1) {
        a0.x += __shfl_xor_sync(0xffffffffu, a0.x, off);
        a0.y += __shfl_xor_sync(0xffffffffu, a0.y, off);
        a0.z += __shfl_xor_sync(0xffffffffu, a0.z, off);
        a0.w += __shfl_xor_sync(0xffffffffu, a0.w, off);
        a1.x += __shfl_xor_sync(0xffffffffu, a1.x, off);
        a1.y += __shfl_xor_sync(0xffffffffu, a1.y, off);
        a1.z += __shfl_xor_sync(0xffffffffu, a1.z, off);
        a1.w += __shfl_xor_sync(0xffffffffu, a1.w, off);
        a2.x += __shfl_xor_sync(0xffffffffu, a2.x, off);
        a2.y += __shfl_xor_sync(0xffffffffu, a2.y, off);
        a2.z += __shfl_xor_sync(0xffffffffu, a2.z, off);
        a2.w += __shfl_xor_sync(0xffffffffu, a2.w, off);
    }
    if (grp == 0) {
        float4* ar = (float4*)(g_agg + (long long)node * HID);
        ar[l8] = a0; ar[l8 + 8] = a1; ar[l8 + 16] = a2;
    }
}

// ---------------- GRU: node-pair f32x2, transposed activations ----------------
// 64 nodes/tile, 256 threads: cj = t&31 -> cols {cj, cj+32, cj+64};
// pg = t>>5 in [0,8) -> node pairs {pg, pg+8, pg+16, pg+24} (nodes 2p, 2p+1).
// smem: agg_t[96][66] + h_t[96][66] + wa[96][96] + wb[96][96] + nodes[64]
__global__ __launch_bounds__(256, 1) void k_gru(
    const float* __restrict__ bih, const float* __restrict__ bhh, int it)
{
    extern __shared__ float sm_g[];
    float* agg_t = sm_g;                 // 96*66
    float* h_t   = agg_t + 96 * 66;      // 96*66
    float* wa    = h_t + 96 * 66;        // 9216  [k][j]
    float* wb    = wa + 9216;            // 9216
    int* nodes_s = (int*)(wb + 9216);

    int t = threadIdx.x;
    int cnt = g_cnt[it];
    int tile0 = blockIdx.x * 64;
    if (tile0 >= cnt) return;
    int nvalid = min(64, cnt - tile0);

    if (t < 64) nodes_s[t] = g_order[tile0 + min(t, nvalid - 1)];
    __syncthreads();
    // stage activations transposed: read coalesced, write conflict-deg-2
    for (int idx = t; idx < 64 * 96; idx += 256) {
        int n = idx / 96, c = idx - n * 96;
        int gn = nodes_s[n];
        agg_t[c * 66 + n] = g_agg[gn * HID + c];
        h_t[c * 66 + n]   = g_h[gn * HID + c];
    }

    int cj = t & 31;
    int pg = t >> 5;

    u64 r_g[3][4], z_g[3][4];

    // chunks 0 (reset) and 1 (update)
#pragma unroll
    for (int chunk = 0; chunk < 2; chunk++) {
        __syncthreads();
        const float4* sA = (const float4*)(g_wt_ih + chunk * 9216);
        const float4* sB = (const float4*)(g_wt_hh + chunk * 9216);
        for (int idx = t; idx < 2304; idx += 256) {
            ((float4*)wa)[idx] = sA[idx];
            ((float4*)wb)[idx] = sB[idx];
        }
        __syncthreads();

        u64 acc[3][4];
#pragma unroll
        for (int cc = 0; cc < 3; cc++) {
            int col = cj + 32 * cc;
            float b = bih[chunk * 96 + col] + bhh[chunk * 96 + col];
            u64 bp = pack2(b, b);
#pragma unroll
            for (int q = 0; q < 4; q++) acc[cc][q] = bp;
        }
#pragma unroll 8
        for (int k = 0; k < 96; k++) {
            u64 wad[3], wbd[3];
#pragma unroll
            for (int cc = 0; cc < 3; cc++) {
                float wav = wa[k * 96 + cj + 32 * cc];
                float wbv = wb[k * 96 + cj + 32 * cc];
                wad[cc] = pack2(wav, wav);
                wbd[cc] = pack2(wbv, wbv);
            }
            u64 ap[4], hp[4];
#pragma unroll
            for (int q = 0; q < 4; q++) {
                ap[q] = *(const u64*)&agg_t[k * 66 + 2 * (pg + 8 * q)];
                hp[q] = *(const u64*)&h_t[k * 66 + 2 * (pg + 8 * q)];
            }
#pragma unroll
            for (int cc = 0; cc < 3; cc++)
#pragma unroll
                for (int q = 0; q < 4; q++) {
                    acc[cc][q] = ffma2(wad[cc], ap[q], acc[cc][q]);
                    acc[cc][q] = ffma2(wbd[cc], hp[q], acc[cc][q]);
                }
        }
#pragma unroll
        for (int cc = 0; cc < 3; cc++)
#pragma unroll
            for (int q = 0; q < 4; q++) {
                float2 g = unpack2(acc[cc][q]);
                float s0 = 1.f / (1.f + expf(-g.x));
                float s1 = 1.f / (1.f + expf(-g.y));
                if (chunk == 0) r_g[cc][q] = pack2(s0, s1);
                else            z_g[cc][q] = pack2(s0, s1);
            }
    }

    // chunk 2 (candidate) + epilogue
    {
        __syncthreads();
        const float4* sA = (const float4*)(g_wt_ih + 2 * 9216);
        const float4* sB = (const float4*)(g_wt_hh + 2 * 9216);
        for (int idx = t; idx < 2304; idx += 256) {
            ((float4*)wa)[idx] = sA[idx];
            ((float4*)wb)[idx] = sB[idx];
        }
        __syncthreads();

        u64 ai[3][4], ah[3][4];
#pragma unroll
        for (int cc = 0; cc < 3; cc++) {
            int col = cj + 32 * cc;
            float b1 = bih[192 + col];
            float b2 = bhh[192 + col];
            u64 p1 = pack2(b1, b1), p2 = pack2(b2, b2);
#pragma unroll
            for (int q = 0; q < 4; q++) { ai[cc][q] = p1; ah[cc][q] = p2; }
        }
#pragma unroll 8
        for (int k = 0; k < 96; k++) {
            u64 wad[3], wbd[3];
#pragma unroll
            for (int cc = 0; cc < 3; cc++) {
                float wav = wa[k * 96 + cj + 32 * cc];
                float wbv = wb[k * 96 + cj + 32 * cc];
                wad[cc] = pack2(wav, wav);
                wbd[cc] = pack2(wbv, wbv);
            }
            u64 ap[4], hp[4];
#pragma unroll
            for (int q = 0; q < 4; q++) {
                ap[q] = *(const u64*)&agg_t[k * 66 + 2 * (pg + 8 * q)];
                hp[q] = *(const u64*)&h_t[k * 66 + 2 * (pg + 8 * q)];
            }
#pragma unroll
            for (int cc = 0; cc < 3; cc++)
#pragma unroll
                for (int q = 0; q < 4; q++) {
                    ai[cc][q] = ffma2(wad[cc], ap[q], ai[cc][q]);
                    ah[cc][q] = ffma2(wbd[cc], hp[q], ah[cc][q]);
                }
        }
#pragma unroll
        for (int cc = 0; cc < 3; cc++) {
            int col = cj + 32 * cc;
#pragma unroll
            for (int q = 0; q < 4; q++) {
                int pr = pg + 8 * q;
                float2 vi = unpack2(ai[cc][q]);
                float2 vh = unpack2(ah[cc][q]);
                float2 rr = unpack2(r_g[cc][q]);
                float2 zz = unpack2(z_g[cc][q]);
                float2 hold = *(const float2*)&h_t[col * 66 + 2 * pr];
                float nv0 = tanhf(vi.x + rr.x * vh.x);
                float nv1 = tanhf(vi.y + rr.y * vh.y);
                float h0 = (1.f - zz.x) * nv0 + zz.x * hold.x;
                float h1 = (1.f - zz.y) * nv1 + zz.y * hold.y;
                g_h[nodes_s[2 * pr] * HID + col]     = h0;
                g_h[nodes_s[2 * pr + 1] * HID + col] = h1;
            }
        }
    }
}

// ---------------- output GEMM: h @ w_out + b_out ----------------
__global__ __launch_bounds__(256) void k_out(
    const float* __restrict__ wo, const float* __restrict__ bo,
    float* __restrict__ out)
{
    __shared__ float ws[96 * 64];
    __shared__ float hs[32 * 97];
    int t = threadIdx.x;
    int node0 = blockIdx.x * 32;
    for (int idx = t; idx < 96 * 64; idx += 256) ws[idx] = wo[idx];
    for (int idx = t; idx < 32 * 96; idx += 256) {
        int n = idx / 96, k = idx - n * 96;
        int gn = node0 + n;
        hs[n * 97 + k] = (gn < N_NODES) ? g_h[gn * HID + k] : 0.f;
    }
    __syncthreads();
    int j = t & 63, nt = t >> 6;
    float acc[8];
#pragma unroll
    for (int nn = 0; nn < 8; nn++) acc[nn] = bo[j];
    for (int k = 0; k < 96; k++) {
        float w = ws[k * 64 + j];
#pragma unroll
        for (int nn = 0; nn < 8; nn++)
            acc[nn] += hs[(nt + 4 * nn) * 97 + k] * w;
    }
#pragma unroll
    for (int nn = 0; nn < 8; nn++) {
        int gn = node0 + nt + 4 * nn;
        if (gn < N_NODES) out[gn * OUT_DIM + j] = acc[nn];
    }
}

// ---------------- launch ----------------
extern "C" void kernel_launch(void* const* d_in, const int* in_sizes, int n_in,
                              void* d_out, int out_size)
{
    const float* x    = (const float*)d_in[0];
    const int*   ei   = (const int*)d_in[1];
    const float* w_in = (const float*)d_in[2];
    const float* b_in = (const float*)d_in[3];
    const float* tw1  = (const float*)d_in[4];
    const float* tb1  = (const float*)d_in[5];
    const float* tw2  = (const float*)d_in[6];
    const float* tb2  = (const float*)d_in[7];
    const float* wih  = (const float*)d_in[8];
    const float* whh  = (const float*)d_in[9];
    const float* bih  = (const float*)d_in[10];
    const float* bhh  = (const float*)d_in[11];
    const float* wo   = (const float*)d_in[12];
    const float* bo   = (const float*)d_in[13];
    float* out = (float*)d_out;

    const int smem_in  = (32 * 129 + 128 * 96 + 128 * 16) * 4;      // 73856 B
    const int smem_gru = (96 * 66 * 2 + 9216 * 2) * 4 + 64 * 4;     // 124672 B
    cudaFuncSetAttribute(k_input, cudaFuncAttributeMaxDynamicSharedMemorySize, smem_in);
    cudaFuncSetAttribute(k_gru,   cudaFuncAttributeMaxDynamicSharedMemorySize, smem_gru);

    // launch #4 is what ncu captures -> k_input this round
    k_initwt<<<(N_NODES + 255) / 256, 256>>>(wih, whh);               // 1
    k_deg<<<(N_EDGES + 255) / 256, 256>>>(ei);                        // 2
    k_scan1<<<SCAN_NB, 1024>>>();                                     // 3
    k_input<<<(N_NODES + 31) / 32, 128, smem_in>>>(x, w_in, b_in,     // 4
                                                   tw1, tb1, tw2, tb2);
    k_scan2<<<1, 64>>>();                                             // 5
    k_scan3<<<SCAN_NB, 1024>>>();                                     // 6
    k_csr<<<(N_EDGES + 255) / 256, 256>>>(ei);                        // 7
    k_order<<<(N_NODES + 255) / 256, 256>>>();                        // 8

    for (int it = 0; it < MAX_REC; it++) {
        k_agg<<<(N_NODES + 7) / 8, 256>>>(it);
        k_gru<<<(N_NODES + 63) / 64, 256, smem_gru>>>(bih, bhh, it);
    }
    k_out<<<(N_NODES + 31) / 32, 256>>>(wo, bo, out);
}

// round 4
// speedup vs baseline: 1.2898x; 1.1178x over previous
#include <cuda_runtime.h>
#include <math.h>

#define N_NODES 50000
#define N_EDGES 800000
#define IN_DIM  128
#define HID     96
#define OUT_DIM 64
#define MAX_REC 5
#define SCAN_NB ((N_NODES + 1023) / 1024)   // 49

typedef unsigned long long u64;

// ---------------- scratch (no allocations allowed) ----------------
__device__ float g_h[N_NODES * HID];
__device__ float g_agg[N_NODES * HID];
__device__ int   g_steps[N_NODES];
__device__ int   g_deg[N_NODES];
__device__ int   g_rowoff[N_NODES + 1];
__device__ int   g_cursor[N_NODES];
__device__ int   g_col[N_EDGES];
__device__ int   g_hist[8];
__device__ int   g_bcur[8];
__device__ int   g_order[N_NODES];
__device__ int   g_cnt[8];
__device__ int   g_bsum[64];
__device__ int   g_boff[64];
__device__ float g_wt_ih[3 * HID * HID];   // [chunk][k][j]
__device__ float g_wt_hh[3 * HID * HID];

// ---------------- f32x2 helpers ----------------
__device__ __forceinline__ u64 ffma2(u64 a, u64 b, u64 c) {
    u64 d;
    asm("fma.rn.f32x2 %0, %1, %2, %3;" : "=l"(d) : "l"(a), "l"(b), "l"(c));
    return d;
}
__device__ __forceinline__ u64 pack2(float x, float y) {
    u64 r;
    asm("mov.b64 %0, {%1, %2};" : "=l"(r) : "f"(x), "f"(y));
    return r;
}
__device__ __forceinline__ float2 unpack2(u64 v) {
    float2 r;
    asm("mov.b64 {%0, %1}, %2;" : "=f"(r.x), "=f"(r.y) : "l"(v));
    return r;
}

// ---------------- fused init + weight transpose ----------------
__global__ void k_initwt(const float* __restrict__ wih, const float* __restrict__ whh) {
    int i = blockIdx.x * 256 + threadIdx.x;
    if (i < N_NODES) g_deg[i] = 0;
    if (i < 8) g_hist[i] = 0;
    if (i < 3 * HID * HID) {
        int chunk = i / (HID * HID);
        int r = i - chunk * HID * HID;
        int k = r / HID, j = r - k * HID;
        g_wt_ih[i] = wih[(chunk * HID + j) * HID + k];
        g_wt_hh[i] = whh[(chunk * HID + j) * HID + k];
    }
}

// ---------------- degree histogram ----------------
__global__ void k_deg(const int* __restrict__ ei) {
    int e = blockIdx.x * blockDim.x + threadIdx.x;
    if (e < N_EDGES) atomicAdd(&g_deg[ei[e]], 1);
}

// ---------------- multi-block scan ----------------
__global__ __launch_bounds__(1024) void k_scan1() {
    __shared__ int wsum[32];
    __shared__ int woff[32];
    int t = threadIdx.x, lane = t & 31, wid = t >> 5;
    int i = blockIdx.x * 1024 + t;
    int v = (i < N_NODES) ? g_deg[i] : 0;
    int s = v;
#pragma unroll
    for (int o = 1; o < 32; o <<= 1) {
        int u = __shfl_up_sync(0xffffffffu, s, o);
        if (lane >= o) s += u;
    }
    if (lane == 31) wsum[wid] = s;
    __syncthreads();
    if (wid == 0) {
        int ws = wsum[lane];
        int ss = ws;
#pragma unroll
        for (int o = 1; o < 32; o <<= 1) {
            int u = __shfl_up_sync(0xffffffffu, ss, o);
            if (lane >= o) ss += u;
        }
        woff[lane] = ss - ws;
        if (lane == 31) g_bsum[blockIdx.x] = ss;
    }
    __syncthreads();
    if (i < N_NODES) g_rowoff[i] = s - v + woff[wid];
}

// ---------------- fused input GEMM + relu + tau/steps ----------------
// 256 threads, 64 nodes/block. Weights via LDG (L1-resident).
// smem: xs_t[128][66] transposed activations + ts[128][16] tau weights = ~42KB
__global__ __launch_bounds__(256) void k_input(
    const float* __restrict__ x, const float* __restrict__ w_in,
    const float* __restrict__ b_in, const float* __restrict__ tw1,
    const float* __restrict__ tb1, const float* __restrict__ tw2,
    const float* __restrict__ tb2)
{
    extern __shared__ float sm_in[];
    float* xs_t = sm_in;               // [128][66]
    float* ts   = xs_t + 128 * 66;     // [128][16]
    int t = threadIdx.x;
    int node0 = blockIdx.x * 64;

    for (int idx = t; idx < 128 * 16; idx += 256) ts[idx] = tw1[idx];
    // stage x transposed: xs_t[k][n]
    for (int idx = t; idx < 64 * 128; idx += 256) {
        int n = idx >> 7, k = idx & 127;
        int gn = node0 + n;
        xs_t[k * 66 + n] = (gn < N_NODES) ? x[gn * IN_DIM + k] : 0.f;
    }
    __syncthreads();

    int cj = t & 31;     // cols {cj, cj+32, cj+64}
    int pg = t >> 5;     // node pairs {pg, pg+8, pg+16, pg+24}

    u64 acc[3][4];
#pragma unroll
    for (int cc = 0; cc < 3; cc++) {
        float b = b_in[cj + 32 * cc];
        u64 bp = pack2(b, b);
#pragma unroll
        for (int q = 0; q < 4; q++) acc[cc][q] = bp;
    }
#pragma unroll 4
    for (int k = 0; k < 128; k++) {
        u64 wd[3];
#pragma unroll
        for (int cc = 0; cc < 3; cc++) {
            float w = __ldg(&w_in[k * 96 + cj + 32 * cc]);
            wd[cc] = pack2(w, w);
        }
        u64 ap[4];
#pragma unroll
        for (int q = 0; q < 4; q++)
            ap[q] = *(const u64*)&xs_t[k * 66 + 2 * (pg + 8 * q)];
#pragma unroll
        for (int cc = 0; cc < 3; cc++)
#pragma unroll
            for (int q = 0; q < 4; q++)
                acc[cc][q] = ffma2(wd[cc], ap[q], acc[cc][q]);
    }
#pragma unroll
    for (int cc = 0; cc < 3; cc++) {
        int col = cj + 32 * cc;
#pragma unroll
        for (int q = 0; q < 4; q++) {
            int n0 = node0 + 2 * (pg + 8 * q);
            float2 g = unpack2(acc[cc][q]);
            if (n0 < N_NODES)     g_h[n0 * HID + col]       = fmaxf(g.x, 0.f);
            if (n0 + 1 < N_NODES) g_h[(n0 + 1) * HID + col] = fmaxf(g.y, 0.f);
        }
    }

    // tau: 4 threads per node, 4 hidden cols each
    {
        int tn = t >> 2;          // node within tile [0,64)
        int tj = t & 3;           // hidden col group {tj, tj+4, tj+8, tj+12}
        int gn = node0 + tn;
        float hh[4];
#pragma unroll
        for (int u = 0; u < 4; u++) hh[u] = tb1[tj + 4 * u];
#pragma unroll 4
        for (int k = 0; k < 128; k++) {
            float xv = xs_t[k * 66 + tn];
#pragma unroll
            for (int u = 0; u < 4; u++)
                hh[u] += xv * ts[k * 16 + tj + 4 * u];
        }
        float s = 0.f;
#pragma unroll
        for (int u = 0; u < 4; u++)
            s += fmaxf(hh[u], 0.f) * tw2[tj + 4 * u];
        s += __shfl_xor_sync(0xffffffffu, s, 1);
        s += __shfl_xor_sync(0xffffffffu, s, 2);
        if (tj == 0 && gn < N_NODES) {
            s += tb2[0];
            float sp = fmaxf(s, 0.f) + log1pf(expf(-fabsf(s)));
            float inv = 1.0f / sp;
            int st = (inv >= (float)MAX_REC) ? MAX_REC : (int)inv;
            g_steps[gn] = st;
            atomicAdd(&g_hist[st], 1);
        }
    }
}

__global__ void k_scan2() {
    __shared__ int sh[64];
    int t = threadIdx.x;
    sh[t] = (t < SCAN_NB) ? g_bsum[t] : 0;
    __syncthreads();
    if (t == 0) {
        int run = 0;
        for (int b = 0; b < SCAN_NB; b++) { g_boff[b] = run; run += sh[b]; }
        g_rowoff[N_NODES] = run;
        int suffix = 0;
        int start[6];
        for (int s = 5; s >= 0; s--) { start[s] = suffix; suffix += g_hist[s]; }
        for (int s = 0; s < 6; s++) g_bcur[s] = start[s];
        for (int it = 0; it < 5; it++) g_cnt[it] = start[it];
    }
}

__global__ __launch_bounds__(1024) void k_scan3() {
    int i = blockIdx.x * 1024 + threadIdx.x;
    if (i < N_NODES) {
        int v = g_rowoff[i] + g_boff[blockIdx.x];
        g_rowoff[i] = v;
        g_cursor[i] = v;
    }
}

// ---------------- CSR fill ----------------
__global__ void k_csr(const int* __restrict__ ei) {
    int e = blockIdx.x * blockDim.x + threadIdx.x;
    if (e < N_EDGES) {
        int r = ei[e];
        int c = ei[N_EDGES + e];
        int pos = atomicAdd(&g_cursor[r], 1);
        g_col[pos] = c;
    }
}

// ---------------- counting sort by steps (descending) ----------------
__global__ void k_order() {
    int i = blockIdx.x * blockDim.x + threadIdx.x;
    if (i < N_NODES) {
        int s = g_steps[i];
        int pos = atomicAdd(&g_bcur[s], 1);
        g_order[pos] = i;
    }
}

// ---------------- edge aggregation: warp/node, 4 edges in flight ----------------
__global__ __launch_bounds__(256) void k_agg(int it) {
    int w = blockIdx.x * 8 + (threadIdx.x >> 5);
    if (w >= g_cnt[it]) return;
    int node = g_order[w];
    int lane = threadIdx.x & 31;
    int grp = lane >> 3;
    int l8  = lane & 7;
    int base = g_rowoff[node], end = g_rowoff[node + 1];

    const float4* hi4 = (const float4*)(g_h + node * HID);
    float4 hi0 = hi4[l8], hi1 = hi4[l8 + 8], hi2 = hi4[l8 + 16];
    float4 a0 = {0,0,0,0}, a1 = {0,0,0,0}, a2 = {0,0,0,0};

    for (int e = base + grp; e < end; e += 4) {
        int cc = g_col[e];
        const float4* hp = (const float4*)(g_h + cc * HID);
        float4 v0 = hp[l8], v1 = hp[l8 + 8], v2 = hp[l8 + 16];
        a0.x += fabsf(v0.x - hi0.x); a0.y += fabsf(v0.y - hi0.y);
        a0.z += fabsf(v0.z - hi0.z); a0.w += fabsf(v0.w - hi0.w);
        a1.x += fabsf(v1.x - hi1.x); a1.y += fabsf(v1.y - hi1.y);
        a1.z += fabsf(v1.z - hi1.z); a1.w += fabsf(v1.w - hi1.w);
        a2.x += fabsf(v2.x - hi2.x); a2.y += fabsf(v2.y - hi2.y);
        a2.z += fabsf(v2.z - hi2.z); a2.w += fabsf(v2.w - hi2.w);
    }
#pragma unroll
    for (int off = 8; off < 32; off <<= 1) {
        a0.x += __shfl_xor_sync(0xffffffffu, a0.x, off);
        a0.y += __shfl_xor_sync(0xffffffffu, a0.y, off);
        a0.z += __shfl_xor_sync(0xffffffffu, a0.z, off);
        a0.w += __shfl_xor_sync(0xffffffffu, a0.w, off);
        a1.x += __shfl_xor_sync(0xffffffffu, a1.x, off);
        a1.y += __shfl_xor_sync(0xffffffffu, a1.y, off);
        a1.z += __shfl_xor_sync(0xffffffffu, a1.z, off);
        a1.w += __shfl_xor_sync(0xffffffffu, a1.w, off);
        a2.x += __shfl_xor_sync(0xffffffffu, a2.x, off);
        a2.y += __shfl_xor_sync(0xffffffffu, a2.y, off);
        a2.z += __shfl_xor_sync(0xffffffffu, a2.z, off);
        a2.w += __shfl_xor_sync(0xffffffffu, a2.w, off);
    }
    if (grp == 0) {
        float4* ar = (float4*)(g_agg + (long long)node * HID);
        ar[l8] = a0; ar[l8 + 8] = a1; ar[l8 + 16] = a2;
    }
}

// ---------------- GRU: node-pair f32x2, transposed activations ----------------
__global__ __launch_bounds__(256, 1) void k_gru(
    const float* __restrict__ bih, const float* __restrict__ bhh, int it)
{
    extern __shared__ float sm_g[];
    float* agg_t = sm_g;                 // 96*66
    float* h_t   = agg_t + 96 * 66;      // 96*66
    float* wa    = h_t + 96 * 66;        // 9216  [k][j]
    float* wb    = wa + 9216;            // 9216
    int* nodes_s = (int*)(wb + 9216);

    int t = threadIdx.x;
    int cnt = g_cnt[it];
    int tile0 = blockIdx.x * 64;
    if (tile0 >= cnt) return;
    int nvalid = min(64, cnt - tile0);

    if (t < 64) nodes_s[t] = g_order[tile0 + min(t, nvalid - 1)];
    __syncthreads();
    for (int idx = t; idx < 64 * 96; idx += 256) {
        int n = idx / 96, c = idx - n * 96;
        int gn = nodes_s[n];
        agg_t[c * 66 + n] = g_agg[gn * HID + c];
        h_t[c * 66 + n]   = g_h[gn * HID + c];
    }

    int cj = t & 31;
    int pg = t >> 5;

    u64 r_g[3][4], z_g[3][4];

#pragma unroll
    for (int chunk = 0; chunk < 2; chunk++) {
        __syncthreads();
        const float4* sA = (const float4*)(g_wt_ih + chunk * 9216);
        const float4* sB = (const float4*)(g_wt_hh + chunk * 9216);
        for (int idx = t; idx < 2304; idx += 256) {
            ((float4*)wa)[idx] = sA[idx];
            ((float4*)wb)[idx] = sB[idx];
        }
        __syncthreads();

        u64 acc[3][4];
#pragma unroll
        for (int cc = 0; cc < 3; cc++) {
            int col = cj + 32 * cc;
            float b = bih[chunk * 96 + col] + bhh[chunk * 96 + col];
            u64 bp = pack2(b, b);
#pragma unroll
            for (int q = 0; q < 4; q++) acc[cc][q] = bp;
        }
#pragma unroll 8
        for (int k = 0; k < 96; k++) {
            u64 wad[3], wbd[3];
#pragma unroll
            for (int cc = 0; cc < 3; cc++) {
                float wav = wa[k * 96 + cj + 32 * cc];
                float wbv = wb[k * 96 + cj + 32 * cc];
                wad[cc] = pack2(wav, wav);
                wbd[cc] = pack2(wbv, wbv);
            }
            u64 ap[4], hp[4];
#pragma unroll
            for (int q = 0; q < 4; q++) {
                ap[q] = *(const u64*)&agg_t[k * 66 + 2 * (pg + 8 * q)];
                hp[q] = *(const u64*)&h_t[k * 66 + 2 * (pg + 8 * q)];
            }
#pragma unroll
            for (int cc = 0; cc < 3; cc++)
#pragma unroll
                for (int q = 0; q < 4; q++) {
                    acc[cc][q] = ffma2(wad[cc], ap[q], acc[cc][q]);
                    acc[cc][q] = ffma2(wbd[cc], hp[q], acc[cc][q]);
                }
        }
#pragma unroll
        for (int cc = 0; cc < 3; cc++)
#pragma unroll
            for (int q = 0; q < 4; q++) {
                float2 g = unpack2(acc[cc][q]);
                float s0 = 1.f / (1.f + expf(-g.x));
                float s1 = 1.f / (1.f + expf(-g.y));
                if (chunk == 0) r_g[cc][q] = pack2(s0, s1);
                else            z_g[cc][q] = pack2(s0, s1);
            }
    }

    {
        __syncthreads();
        const float4* sA = (const float4*)(g_wt_ih + 2 * 9216);
        const float4* sB = (const float4*)(g_wt_hh + 2 * 9216);
        for (int idx = t; idx < 2304; idx += 256) {
            ((float4*)wa)[idx] = sA[idx];
            ((float4*)wb)[idx] = sB[idx];
        }
        __syncthreads();

        u64 ai[3][4], ah[3][4];
#pragma unroll
        for (int cc = 0; cc < 3; cc++) {
            int col = cj + 32 * cc;
            float b1 = bih[192 + col];
            float b2 = bhh[192 + col];
            u64 p1 = pack2(b1, b1), p2 = pack2(b2, b2);
#pragma unroll
            for (int q = 0; q < 4; q++) { ai[cc][q] = p1; ah[cc][q] = p2; }
        }
#pragma unroll 8
        for (int k = 0; k < 96; k++) {
            u64 wad[3], wbd[3];
#pragma unroll
            for (int cc = 0; cc < 3; cc++) {
                float wav = wa[k * 96 + cj + 32 * cc];
                float wbv = wb[k * 96 + cj + 32 * cc];
                wad[cc] = pack2(wav, wav);
                wbd[cc] = pack2(wbv, wbv);
            }
            u64 ap[4], hp[4];
#pragma unroll
            for (int q = 0; q < 4; q++) {
                ap[q] = *(const u64*)&agg_t[k * 66 + 2 * (pg + 8 * q)];
                hp[q] = *(const u64*)&h_t[k * 66 + 2 * (pg + 8 * q)];
            }
#pragma unroll
            for (int cc = 0; cc < 3; cc++)
#pragma unroll
                for (int q = 0; q < 4; q++) {
                    ai[cc][q] = ffma2(wad[cc], ap[q], ai[cc][q]);
                    ah[cc][q] = ffma2(wbd[cc], hp[q], ah[cc][q]);
                }
        }
#pragma unroll
        for (int cc = 0; cc < 3; cc++) {
            int col = cj + 32 * cc;
#pragma unroll
            for (int q = 0; q < 4; q++) {
                int pr = pg + 8 * q;
                float2 vi = unpack2(ai[cc][q]);
                float2 vh = unpack2(ah[cc][q]);
                float2 rr = unpack2(r_g[cc][q]);
                float2 zz = unpack2(z_g[cc][q]);
                float2 hold = *(const float2*)&h_t[col * 66 + 2 * pr];
                float nv0 = tanhf(vi.x + rr.x * vh.x);
                float nv1 = tanhf(vi.y + rr.y * vh.y);
                float h0 = (1.f - zz.x) * nv0 + zz.x * hold.x;
                float h1 = (1.f - zz.y) * nv1 + zz.y * hold.y;
                g_h[nodes_s[2 * pr] * HID + col]     = h0;
                g_h[nodes_s[2 * pr + 1] * HID + col] = h1;
            }
        }
    }
}

// ---------------- output GEMM: h @ w_out + b_out ----------------
__global__ __launch_bounds__(256) void k_out(
    const float* __restrict__ wo, const float* __restrict__ bo,
    float* __restrict__ out)
{
    __shared__ float ws[96 * 64];
    __shared__ float hs[32 * 97];
    int t = threadIdx.x;
    int node0 = blockIdx.x * 32;
    for (int idx = t; idx < 96 * 64; idx += 256) ws[idx] = wo[idx];
    for (int idx = t; idx < 32 * 96; idx += 256) {
        int n = idx / 96, k = idx - n * 96;
        int gn = node0 + n;
        hs[n * 97 + k] = (gn < N_NODES) ? g_h[gn * HID + k] : 0.f;
    }
    __syncthreads();
    int j = t & 63, nt = t >> 6;
    float acc[8];
#pragma unroll
    for (int nn = 0; nn < 8; nn++) acc[nn] = bo[j];
    for (int k = 0; k < 96; k++) {
        float w = ws[k * 64 + j];
#pragma unroll
        for (int nn = 0; nn < 8; nn++)
            acc[nn] += hs[(nt + 4 * nn) * 97 + k] * w;
    }
#pragma unroll
    for (int nn = 0; nn < 8; nn++) {
        int gn = node0 + nt + 4 * nn;
        if (gn < N_NODES) out[gn * OUT_DIM + j] = acc[nn];
    }
}

// ---------------- launch ----------------
extern "C" void kernel_launch(void* const* d_in, const int* in_sizes, int n_in,
                              void* d_out, int out_size)
{
    const float* x    = (const float*)d_in[0];
    const int*   ei   = (const int*)d_in[1];
    const float* w_in = (const float*)d_in[2];
    const float* b_in = (const float*)d_in[3];
    const float* tw1  = (const float*)d_in[4];
    const float* tb1  = (const float*)d_in[5];
    const float* tw2  = (const float*)d_in[6];
    const float* tb2  = (const float*)d_in[7];
    const float* wih  = (const float*)d_in[8];
    const float* whh  = (const float*)d_in[9];
    const float* bih  = (const float*)d_in[10];
    const float* bhh  = (const float*)d_in[11];
    const float* wo   = (const float*)d_in[12];
    const float* bo   = (const float*)d_in[13];
    float* out = (float*)d_out;

    const int smem_in  = (128 * 66 + 128 * 16) * 4;                 // 41984 B
    const int smem_gru = (96 * 66 * 2 + 9216 * 2) * 4 + 64 * 4;     // 124672 B
    cudaFuncSetAttribute(k_input, cudaFuncAttributeMaxDynamicSharedMemorySize, smem_in);
    cudaFuncSetAttribute(k_gru,   cudaFuncAttributeMaxDynamicSharedMemorySize, smem_gru);

    // launch #4 is what ncu captures -> k_input (verify the fix)
    k_initwt<<<(N_NODES + 255) / 256, 256>>>(wih, whh);               // 1
    k_deg<<<(N_EDGES + 255) / 256, 256>>>(ei);                        // 2
    k_scan1<<<SCAN_NB, 1024>>>();                                     // 3
    k_input<<<(N_NODES + 63) / 64, 256, smem_in>>>(x, w_in, b_in,     // 4
                                                   tw1, tb1, tw2, tb2);
    k_scan2<<<1, 64>>>();                                             // 5
    k_scan3<<<SCAN_NB, 1024>>>();                                     // 6
    k_csr<<<(N_EDGES + 255) / 256, 256>>>(ei);                        // 7
    k_order<<<(N_NODES + 255) / 256, 256>>>();                        // 8

    for (int it = 0; it < MAX_REC; it++) {
        k_agg<<<(N_NODES + 7) / 8, 256>>>(it);
        k_gru<<<(N_NODES + 63) / 64, 256, smem_gru>>>(bih, bhh, it);
    }
    k_out<<<(N_NODES + 31) / 32, 256>>>(wo, bo, out);
}

// round 5
// speedup vs baseline: 1.3425x; 1.0408x over previous
#include <cuda_runtime.h>
#include <math.h>

#define N_NODES 50000
#define N_EDGES 800000
#define IN_DIM  128
#define HID     96
#define OUT_DIM 64
#define MAX_REC 5
#define SCAN_NB ((N_NODES + 1023) / 1024)   // 49

typedef unsigned long long u64;

// ---------------- scratch (no allocations allowed) ----------------
__device__ float g_h[N_NODES * HID];
__device__ float g_agg[N_NODES * HID];
__device__ int   g_steps[N_NODES];
__device__ int   g_deg[N_NODES];
__device__ int   g_rowoff[N_NODES + 1];
__device__ int   g_cursor[N_NODES];
__device__ int   g_col[N_EDGES];
__device__ int   g_hist[8];
__device__ int   g_bcur[8];
__device__ int   g_order[N_NODES];
__device__ int   g_cnt[8];
__device__ int   g_bsum[64];
__device__ int   g_boff[64];
__device__ float g_wt_ih[3 * HID * HID];   // [chunk][k][j]
__device__ float g_wt_hh[3 * HID * HID];

// ---------------- f32x2 helpers ----------------
__device__ __forceinline__ u64 ffma2(u64 a, u64 b, u64 c) {
    u64 d;
    asm("fma.rn.f32x2 %0, %1, %2, %3;" : "=l"(d) : "l"(a), "l"(b), "l"(c));
    return d;
}
__device__ __forceinline__ u64 pack2(float x, float y) {
    u64 r;
    asm("mov.b64 %0, {%1, %2};" : "=l"(r) : "f"(x), "f"(y));
    return r;
}
__device__ __forceinline__ float2 unpack2(u64 v) {
    float2 r;
    asm("mov.b64 {%0, %1}, %2;" : "=f"(r.x), "=f"(r.y) : "l"(v));
    return r;
}

// ---------------- fused init + weight transpose ----------------
__global__ void k_initwt(const float* __restrict__ wih, const float* __restrict__ whh) {
    int i = blockIdx.x * 256 + threadIdx.x;
    if (i < N_NODES) g_deg[i] = 0;
    if (i < 8) g_hist[i] = 0;
    if (i < 3 * HID * HID) {
        int chunk = i / (HID * HID);
        int r = i - chunk * HID * HID;
        int k = r / HID, j = r - k * HID;
        g_wt_ih[i] = wih[(chunk * HID + j) * HID + k];
        g_wt_hh[i] = whh[(chunk * HID + j) * HID + k];
    }
}

// ---------------- degree histogram ----------------
__global__ void k_deg(const int* __restrict__ ei) {
    int e = blockIdx.x * blockDim.x + threadIdx.x;
    if (e < N_EDGES) atomicAdd(&g_deg[ei[e]], 1);
}

// ---------------- multi-block scan ----------------
__global__ __launch_bounds__(1024) void k_scan1() {
    __shared__ int wsum[32];
    __shared__ int woff[32];
    int t = threadIdx.x, lane = t & 31, wid = t >> 5;
    int i = blockIdx.x * 1024 + t;
    int v = (i < N_NODES) ? g_deg[i] : 0;
    int s = v;
#pragma unroll
    for (int o = 1; o < 32; o <<= 1) {
        int u = __shfl_up_sync(0xffffffffu, s, o);
        if (lane >= o) s += u;
    }
    if (lane == 31) wsum[wid] = s;
    __syncthreads();
    if (wid == 0) {
        int ws = wsum[lane];
        int ss = ws;
#pragma unroll
        for (int o = 1; o < 32; o <<= 1) {
            int u = __shfl_up_sync(0xffffffffu, ss, o);
            if (lane >= o) ss += u;
        }
        woff[lane] = ss - ws;
        if (lane == 31) g_bsum[blockIdx.x] = ss;
    }
    __syncthreads();
    if (i < N_NODES) g_rowoff[i] = s - v + woff[wid];
}

// ---------------- fused input GEMM + relu + tau/steps ----------------
__global__ __launch_bounds__(256) void k_input(
    const float* __restrict__ x, const float* __restrict__ w_in,
    const float* __restrict__ b_in, const float* __restrict__ tw1,
    const float* __restrict__ tb1, const float* __restrict__ tw2,
    const float* __restrict__ tb2)
{
    extern __shared__ float sm_in[];
    float* xs_t = sm_in;               // [128][66]
    float* ts   = xs_t + 128 * 66;     // [128][16]
    int t = threadIdx.x;
    int node0 = blockIdx.x * 64;

    for (int idx = t; idx < 128 * 16; idx += 256) ts[idx] = tw1[idx];
    for (int idx = t; idx < 64 * 128; idx += 256) {
        int n = idx >> 7, k = idx & 127;
        int gn = node0 + n;
        xs_t[k * 66 + n] = (gn < N_NODES) ? x[gn * IN_DIM + k] : 0.f;
    }
    __syncthreads();

    int cj = t & 31;     // cols {cj, cj+32, cj+64}
    int pg = t >> 5;     // node pairs {pg, pg+8, pg+16, pg+24}

    u64 acc[3][4];
#pragma unroll
    for (int cc = 0; cc < 3; cc++) {
        float b = b_in[cj + 32 * cc];
        u64 bp = pack2(b, b);
#pragma unroll
        for (int q = 0; q < 4; q++) acc[cc][q] = bp;
    }
#pragma unroll 8
    for (int k = 0; k < 128; k++) {
        u64 wd[3];
#pragma unroll
        for (int cc = 0; cc < 3; cc++) {
            float w = __ldg(&w_in[k * 96 + cj + 32 * cc]);
            wd[cc] = pack2(w, w);
        }
        u64 ap[4];
#pragma unroll
        for (int q = 0; q < 4; q++)
            ap[q] = *(const u64*)&xs_t[k * 66 + 2 * (pg + 8 * q)];
#pragma unroll
        for (int cc = 0; cc < 3; cc++)
#pragma unroll
            for (int q = 0; q < 4; q++)
                acc[cc][q] = ffma2(wd[cc], ap[q], acc[cc][q]);
    }
#pragma unroll
    for (int cc = 0; cc < 3; cc++) {
        int col = cj + 32 * cc;
#pragma unroll
        for (int q = 0; q < 4; q++) {
            int n0 = node0 + 2 * (pg + 8 * q);
            float2 g = unpack2(acc[cc][q]);
            if (n0 < N_NODES)     g_h[n0 * HID + col]       = fmaxf(g.x, 0.f);
            if (n0 + 1 < N_NODES) g_h[(n0 + 1) * HID + col] = fmaxf(g.y, 0.f);
        }
    }

    // tau: 4 threads per node
    {
        int tn = t >> 2;
        int tj = t & 3;
        int gn = node0 + tn;
        float hh[4];
#pragma unroll
        for (int u = 0; u < 4; u++) hh[u] = tb1[tj + 4 * u];
#pragma unroll 4
        for (int k = 0; k < 128; k++) {
            float xv = xs_t[k * 66 + tn];
#pragma unroll
            for (int u = 0; u < 4; u++)
                hh[u] += xv * ts[k * 16 + tj + 4 * u];
        }
        float s = 0.f;
#pragma unroll
        for (int u = 0; u < 4; u++)
            s += fmaxf(hh[u], 0.f) * tw2[tj + 4 * u];
        s += __shfl_xor_sync(0xffffffffu, s, 1);
        s += __shfl_xor_sync(0xffffffffu, s, 2);
        if (tj == 0 && gn < N_NODES) {
            s += tb2[0];
            float sp = fmaxf(s, 0.f) + log1pf(expf(-fabsf(s)));
            float inv = 1.0f / sp;
            int st = (inv >= (float)MAX_REC) ? MAX_REC : (int)inv;
            g_steps[gn] = st;
            atomicAdd(&g_hist[st], 1);
        }
    }
}

__global__ void k_scan2() {
    __shared__ int sh[64];
    int t = threadIdx.x;
    sh[t] = (t < SCAN_NB) ? g_bsum[t] : 0;
    __syncthreads();
    if (t == 0) {
        int run = 0;
        for (int b = 0; b < SCAN_NB; b++) { g_boff[b] = run; run += sh[b]; }
        g_rowoff[N_NODES] = run;
        int suffix = 0;
        int start[6];
        for (int s = 5; s >= 0; s--) { start[s] = suffix; suffix += g_hist[s]; }
        for (int s = 0; s < 6; s++) g_bcur[s] = start[s];
        for (int it = 0; it < 5; it++) g_cnt[it] = start[it];
    }
}

// scan3 + order fused
__global__ __launch_bounds__(1024) void k_scan3() {
    int i = blockIdx.x * 1024 + threadIdx.x;
    if (i < N_NODES) {
        int v = g_rowoff[i] + g_boff[blockIdx.x];
        g_rowoff[i] = v;
        g_cursor[i] = v;
        int s = g_steps[i];
        int pos = atomicAdd(&g_bcur[s], 1);
        g_order[pos] = i;
    }
}

// ---------------- CSR fill ----------------
__global__ void k_csr(const int* __restrict__ ei) {
    int e = blockIdx.x * blockDim.x + threadIdx.x;
    if (e < N_EDGES) {
        int r = ei[e];
        int c = ei[N_EDGES + e];
        int pos = atomicAdd(&g_cursor[r], 1);
        g_col[pos] = c;
    }
}

// ---------------- edge aggregation: warp/node, 8 edges in flight ----------------
__global__ __launch_bounds__(256) void k_agg(int it) {
    int w = blockIdx.x * 8 + (threadIdx.x >> 5);
    if (w >= g_cnt[it]) return;
    int node = g_order[w];
    int lane = threadIdx.x & 31;
    int grp = lane >> 2;       // 8 edge subgroups of 4 lanes
    int l4  = lane & 3;        // lane's float4 slots: l4, l4+4, ..., l4+20
    int base = g_rowoff[node], end = g_rowoff[node + 1];

    const float4* hi4 = (const float4*)(g_h + node * HID);
    float4 hi[6], acc[6];
#pragma unroll
    for (int u = 0; u < 6; u++) {
        hi[u] = hi4[l4 + 4 * u];
        acc[u] = make_float4(0.f, 0.f, 0.f, 0.f);
    }

    for (int e = base + grp; e < end; e += 8) {
        int cc = __ldg(&g_col[e]);
        const float4* hp = (const float4*)(g_h + cc * HID);
#pragma unroll
        for (int u = 0; u < 6; u++) {
            float4 v = hp[l4 + 4 * u];
            acc[u].x += fabsf(v.x - hi[u].x);
            acc[u].y += fabsf(v.y - hi[u].y);
            acc[u].z += fabsf(v.z - hi[u].z);
            acc[u].w += fabsf(v.w - hi[u].w);
        }
    }
#pragma unroll
    for (int off = 4; off < 32; off <<= 1) {
#pragma unroll
        for (int u = 0; u < 6; u++) {
            acc[u].x += __shfl_xor_sync(0xffffffffu, acc[u].x, off);
            acc[u].y += __shfl_xor_sync(0xffffffffu, acc[u].y, off);
            acc[u].z += __shfl_xor_sync(0xffffffffu, acc[u].z, off);
            acc[u].w += __shfl_xor_sync(0xffffffffu, acc[u].w, off);
        }
    }
    if (grp == 0) {
        float4* ar = (float4*)(g_agg + (long long)node * HID);
#pragma unroll
        for (int u = 0; u < 6; u++) ar[l4 + 4 * u] = acc[u];
    }
}

// ---------------- GRU v3: fused r+z pass, col-pair weights, scalar acts ----------
// 64 nodes/tile, 256 threads. cp = t&15 -> col-pairs {cp, cp+16, cp+32};
// ng = t>>4 -> nodes {4ng..4ng+3}.
// smem: agg_s[64][100] + h_s[64][100] + w0a/w0b/w1a/w1b[96][96] + nodes[64]
__global__ __launch_bounds__(256, 1) void k_gru(
    const float* __restrict__ bih, const float* __restrict__ bhh, int it)
{
    extern __shared__ float sm_g[];
    float* agg_s = sm_g;                 // 6400
    float* h_s   = agg_s + 6400;         // 6400
    float* w0a   = h_s + 6400;           // 9216 (r: ih)
    float* w0b   = w0a + 9216;           // 9216 (r: hh)
    float* w1a   = w0b + 9216;           // 9216 (z: ih)
    float* w1b   = w1a + 9216;           // 9216 (z: hh)
    int* nodes_s = (int*)(w1b + 9216);

    int t = threadIdx.x;
    int cnt = g_cnt[it];
    int tile0 = blockIdx.x * 64;
    if (tile0 >= cnt) return;
    int nvalid = min(64, cnt - tile0);

    if (t < 64) nodes_s[t] = g_order[tile0 + min(t, nvalid - 1)];
    __syncthreads();
    // stage acts (coalesced, untransposed) + r/z weights (4 matrices)
    for (int idx = t; idx < 64 * 24; idx += 256) {
        int n = idx / 24, c4 = idx - n * 24;
        int gn = nodes_s[n];
        ((float4*)(agg_s + n * 100))[c4] = ((const float4*)(g_agg + gn * HID))[c4];
        ((float4*)(h_s + n * 100))[c4]   = ((const float4*)(g_h + gn * HID))[c4];
    }
    for (int idx = t; idx < 2304; idx += 256) {
        ((float4*)w0a)[idx] = ((const float4*)g_wt_ih)[idx];
        ((float4*)w0b)[idx] = ((const float4*)g_wt_hh)[idx];
        ((float4*)w1a)[idx] = ((const float4*)(g_wt_ih + 9216))[idx];
        ((float4*)w1b)[idx] = ((const float4*)(g_wt_hh + 9216))[idx];
    }
    __syncthreads();

    int cp = t & 15;     // col-pairs {cp, cp+16, cp+32} (cols 2p, 2p+1)
    int ng = t >> 4;     // nodes 4ng..4ng+3
    int nb = 4 * ng;

    u64 accR[3][4], accZ[3][4];
#pragma unroll
    for (int cc = 0; cc < 3; cc++) {
        int c2 = 2 * (cp + 16 * cc);
        float2 bi0 = *(const float2*)&bih[c2];
        float2 bh0 = *(const float2*)&bhh[c2];
        float2 bi1 = *(const float2*)&bih[96 + c2];
        float2 bh1 = *(const float2*)&bhh[96 + c2];
        u64 bR = pack2(bi0.x + bh0.x, bi0.y + bh0.y);
        u64 bZ = pack2(bi1.x + bh1.x, bi1.y + bh1.y);
#pragma unroll
        for (int q = 0; q < 4; q++) { accR[cc][q] = bR; accZ[cc][q] = bZ; }
    }
#pragma unroll 4
    for (int k = 0; k < 96; k++) {
        u64 wra[3], wrb[3], wza[3], wzb[3];
#pragma unroll
        for (int cc = 0; cc < 3; cc++) {
            int o = k * 96 + 2 * (cp + 16 * cc);
            wra[cc] = *(const u64*)&w0a[o];
            wrb[cc] = *(const u64*)&w0b[o];
            wza[cc] = *(const u64*)&w1a[o];
            wzb[cc] = *(const u64*)&w1b[o];
        }
        u64 a2[4], h2[4];
#pragma unroll
        for (int q = 0; q < 4; q++) {
            float a  = agg_s[(nb + q) * 100 + k];
            float hv = h_s[(nb + q) * 100 + k];
            a2[q] = pack2(a, a);
            h2[q] = pack2(hv, hv);
        }
#pragma unroll
        for (int cc = 0; cc < 3; cc++)
#pragma unroll
            for (int q = 0; q < 4; q++) {
                accR[cc][q] = ffma2(wra[cc], a2[q], accR[cc][q]);
                accR[cc][q] = ffma2(wrb[cc], h2[q], accR[cc][q]);
                accZ[cc][q] = ffma2(wza[cc], a2[q], accZ[cc][q]);
                accZ[cc][q] = ffma2(wzb[cc], h2[q], accZ[cc][q]);
            }
    }
    u64 r_g[3][4], z_g[3][4];
#pragma unroll
    for (int cc = 0; cc < 3; cc++)
#pragma unroll
        for (int q = 0; q < 4; q++) {
            float2 gr = unpack2(accR[cc][q]);
            float2 gz = unpack2(accZ[cc][q]);
            r_g[cc][q] = pack2(1.f / (1.f + expf(-gr.x)), 1.f / (1.f + expf(-gr.y)));
            z_g[cc][q] = pack2(1.f / (1.f + expf(-gz.x)), 1.f / (1.f + expf(-gz.y)));
        }

    // chunk 2: candidate gate
    __syncthreads();
    for (int idx = t; idx < 2304; idx += 256) {
        ((float4*)w0a)[idx] = ((const float4*)(g_wt_ih + 18432))[idx];
        ((float4*)w0b)[idx] = ((const float4*)(g_wt_hh + 18432))[idx];
    }
    __syncthreads();

    u64 ai[3][4], ah[3][4];
#pragma unroll
    for (int cc = 0; cc < 3; cc++) {
        int c2 = 2 * (cp + 16 * cc);
        float2 b1 = *(const float2*)&bih[192 + c2];
        float2 b2 = *(const float2*)&bhh[192 + c2];
        u64 p1 = pack2(b1.x, b1.y), p2 = pack2(b2.x, b2.y);
#pragma unroll
        for (int q = 0; q < 4; q++) { ai[cc][q] = p1; ah[cc][q] = p2; }
    }
#pragma unroll 4
    for (int k = 0; k < 96; k++) {
        u64 wa[3], wb[3];
#pragma unroll
        for (int cc = 0; cc < 3; cc++) {
            int o = k * 96 + 2 * (cp + 16 * cc);
            wa[cc] = *(const u64*)&w0a[o];
            wb[cc] = *(const u64*)&w0b[o];
        }
        u64 a2[4], h2[4];
#pragma unroll
        for (int q = 0; q < 4; q++) {
            float a  = agg_s[(nb + q) * 100 + k];
            float hv = h_s[(nb + q) * 100 + k];
            a2[q] = pack2(a, a);
            h2[q] = pack2(hv, hv);
        }
#pragma unroll
        for (int cc = 0; cc < 3; cc++)
#pragma unroll
            for (int q = 0; q < 4; q++) {
                ai[cc][q] = ffma2(wa[cc], a2[q], ai[cc][q]);
                ah[cc][q] = ffma2(wb[cc], h2[q], ah[cc][q]);
            }
    }
#pragma unroll
    for (int cc = 0; cc < 3; cc++) {
        int c2 = 2 * (cp + 16 * cc);
#pragma unroll
        for (int q = 0; q < 4; q++) {
            int n = nb + q;
            float2 vi = unpack2(ai[cc][q]);
            float2 vh = unpack2(ah[cc][q]);
            float2 rr = unpack2(r_g[cc][q]);
            float2 zz = unpack2(z_g[cc][q]);
            float hold0 = h_s[n * 100 + c2];
            float hold1 = h_s[n * 100 + c2 + 1];
            float nv0 = tanhf(vi.x + rr.x * vh.x);
            float nv1 = tanhf(vi.y + rr.y * vh.y);
            float h0 = (1.f - zz.x) * nv0 + zz.x * hold0;
            float h1 = (1.f - zz.y) * nv1 + zz.y * hold1;
            *(float2*)&g_h[nodes_s[n] * HID + c2] = make_float2(h0, h1);
        }
    }
}

// ---------------- output GEMM ----------------
__global__ __launch_bounds__(256) void k_out(
    const float* __restrict__ wo, const float* __restrict__ bo,
    float* __restrict__ out)
{
    __shared__ float ws[96 * 64];
    __shared__ float hs[32 * 97];
    int t = threadIdx.x;
    int node0 = blockIdx.x * 32;
    for (int idx = t; idx < 96 * 64; idx += 256) ws[idx] = wo[idx];
    for (int idx = t; idx < 32 * 96; idx += 256) {
        int n = idx / 96, k = idx - n * 96;
        int gn = node0 + n;
        hs[n * 97 + k] = (gn < N_NODES) ? g_h[gn * HID + k] : 0.f;
    }
    __syncthreads();
    int j = t & 63, nt = t >> 6;
    float acc[8];
#pragma unroll
    for (int nn = 0; nn < 8; nn++) acc[nn] = bo[j];
    for (int k = 0; k < 96; k++) {
        float w = ws[k * 64 + j];
#pragma unroll
        for (int nn = 0; nn < 8; nn++)
            acc[nn] += hs[(nt + 4 * nn) * 97 + k] * w;
    }
#pragma unroll
    for (int nn = 0; nn < 8; nn++) {
        int gn = node0 + nt + 4 * nn;
        if (gn < N_NODES) out[gn * OUT_DIM + j] = acc[nn];
    }
}

// ---------------- launch ----------------
extern "C" void kernel_launch(void* const* d_in, const int* in_sizes, int n_in,
                              void* d_out, int out_size)
{
    const float* x    = (const float*)d_in[0];
    const int*   ei   = (const int*)d_in[1];
    const float* w_in = (const float*)d_in[2];
    const float* b_in = (const float*)d_in[3];
    const float* tw1  = (const float*)d_in[4];
    const float* tb1  = (const float*)d_in[5];
    const float* tw2  = (const float*)d_in[6];
    const float* tb2  = (const float*)d_in[7];
    const float* wih  = (const float*)d_in[8];
    const float* whh  = (const float*)d_in[9];
    const float* bih  = (const float*)d_in[10];
    const float* bhh  = (const float*)d_in[11];
    const float* wo   = (const float*)d_in[12];
    const float* bo   = (const float*)d_in[13];
    float* out = (float*)d_out;

    const int smem_in  = (128 * 66 + 128 * 16) * 4;                     // 41984 B
    const int smem_gru = (6400 * 2 + 9216 * 4) * 4 + 64 * 4;            // 198912 B
    cudaFuncSetAttribute(k_input, cudaFuncAttributeMaxDynamicSharedMemorySize, smem_in);
    cudaFuncSetAttribute(k_gru,   cudaFuncAttributeMaxDynamicSharedMemorySize, smem_gru);

    k_initwt<<<(N_NODES + 255) / 256, 256>>>(wih, whh);               // 1
    k_deg<<<(N_EDGES + 255) / 256, 256>>>(ei);                        // 2
    k_scan1<<<SCAN_NB, 1024>>>();                                     // 3
    k_input<<<(N_NODES + 63) / 64, 256, smem_in>>>(x, w_in, b_in,     // 4 (profiled)
                                                   tw1, tb1, tw2, tb2);
    k_scan2<<<1, 64>>>();                                             // 5
    k_scan3<<<SCAN_NB, 1024>>>();                                     // 6 (+order)
    k_csr<<<(N_EDGES + 255) / 256, 256>>>(ei);                        // 7

    for (int it = 0; it < MAX_REC; it++) {
        k_agg<<<(N_NODES + 7) / 8, 256>>>(it);
        k_gru<<<(N_NODES + 63) / 64, 256, smem_gru>>>(bih, bhh, it);
    }
    k_out<<<(N_NODES + 31) / 32, 256>>>(wo, bo, out);
}